// round 4
// baseline (speedup 1.0000x reference)
#include <cuda_runtime.h>
#include <math.h>
#include <stdint.h>

#define HEADS 4
#define DD 256
#define HD 1024            // HEADS * DD

#define MAXND 20000
#define MAXNI 4096
#define MAXED 640000
#define MAXET (MAXED + MAXND)

// ---------------- scratch (device globals; no allocation allowed) ----------
__device__ float g_hd  [(size_t)MAXND * HD];
__device__ float g_hi  [(size_t)MAXNI * HD];
__device__ float g_he  [(size_t)MAXNI * HD];
__device__ float g_ie  [(size_t)MAXNI * DD];
__device__ float g_ee  [(size_t)MAXNI * DD];
__device__ float g_ssrc[(size_t)MAXND * HEADS];
__device__ float g_sdst[(size_t)MAXND * HEADS];
__device__ float g_ssum[MAXND];                  // attention row sums
__device__ int   g_deg [MAXND];
__device__ int   g_off [MAXND + 1];
__device__ int   g_cur [MAXND];
__device__ int   g_csr [MAXET];
__device__ float g_gat [(size_t)MAXND * DD];
__device__ float g_dd  [(size_t)MAXND * DD];
__device__ float g_ii  [(size_t)MAXNI * DD];
__device__ float g_ev  [(size_t)MAXNI * DD];
__device__ float g_S   [(size_t)MAXND * 4096];
__device__ float g_atti[(size_t)MAXND * DD];
__device__ float g_atte[(size_t)MAXND * DD];

// ---------------- helpers ---------------------------------------------------
__device__ __forceinline__ uint32_t f2tf(float f) {
    uint32_t u;
    asm("cvt.rna.tf32.f32 %0, %1;" : "=r"(u) : "f"(f));
    return u;
}
__device__ __forceinline__ uint32_t smem_u32(const void* p) {
    uint32_t a;
    asm("{ .reg .u64 t; cvta.to.shared.u64 t, %1; cvt.u32.u64 %0, t; }"
        : "=r"(a) : "l"(p));
    return a;
}
#define CPASYNC16(d, s, sz) \
    asm volatile("cp.async.cg.shared.global [%0], [%1], 16, %2;" \
                 :: "r"(d), "l"(s), "r"(sz))
#define CPCOMMIT() asm volatile("cp.async.commit_group;")

// ---------------- tf32 tensor-core GEMM, cp.async 2-stage pipeline ----------
// C[M,N] = A[M,K] @ B  (B: [K,N] row-major; [N,K] row-major if TRANSB)
// BM=256, BN=128, BK=16; 256 threads = 8 warps (4x2); warp tile 64x64.
// MODE: 0 = plain, 1 = bias+relu, 2 = exp + rowsum atomics, 3 = divide by rowsum
// Requires K % 16 == 0, N % 128 == 0; M guarded. Dynamic smem 61440 B.
#define TG_SMEM 61440
template<bool TRANSB, int MODE>
__global__ __launch_bounds__(256)
void tgemm(const float* __restrict__ A, const float* __restrict__ B,
           float* __restrict__ C, const float* __restrict__ aux,
           float* __restrict__ rowsum, int M, int N, int K)
{
    extern __shared__ float smp[];
    float* Asm[2] = { smp, smp + 5120 };          // 256*20 each
    float* Bsm[2] = { smp + 10240, smp + 12800 }; // 2560 each

    const int tid  = threadIdx.x;
    const int warp = tid >> 5, lane = tid & 31;
    const int g    = lane >> 2, tig = lane & 3;
    const int wm   = (warp >> 1) * 64;
    const int wn   = (warp & 1) * 64;
    const int row0 = blockIdx.y * 256, col0 = blockIdx.x * 128;

    float c[4][8][4];
#pragma unroll
    for (int i = 0; i < 4; i++)
#pragma unroll
        for (int j = 0; j < 8; j++)
#pragma unroll
            for (int q = 0; q < 4; q++) c[i][j][q] = 0.f;

    uint32_t asb[2] = { smem_u32(Asm[0]), smem_u32(Asm[1]) };
    uint32_t bsb[2] = { smem_u32(Bsm[0]), smem_u32(Bsm[1]) };

    const int nIter = K >> 4;

    auto load_stage = [&](int s, int k0) {
#pragma unroll
        for (int i = 0; i < 4; i++) {        // A: 256 rows x 16 k = 1024 chunks
            int f = tid + 256 * i;
            int row = f >> 2, c4 = (f & 3) * 4;
            int gr = row0 + row;
            const float* src = A + (size_t)(gr < M ? gr : M - 1) * K + k0 + c4;
            CPASYNC16(asb[s] + (row * 20 + c4) * 4, src, (gr < M) ? 16 : 0);
        }
#pragma unroll
        for (int i = 0; i < 2; i++) {        // B: 512 chunks
            int f = tid + 256 * i;
            if (TRANSB) {
                int n = f >> 2, k4 = (f & 3) * 4;
                const float* src = B + (size_t)(col0 + n) * K + k0 + k4;
                CPASYNC16(bsb[s] + (n * 20 + k4) * 4, src, 16);
            } else {
                int k = f >> 5, n4 = (f & 31) * 4;
                const float* src = B + (size_t)(k0 + k) * N + col0 + n4;
                CPASYNC16(bsb[s] + (k * 136 + n4) * 4, src, 16);
            }
        }
        CPCOMMIT();
    };

    load_stage(0, 0);

    for (int it = 0; it < nIter; it++) {
        if (it + 1 < nIter) {
            load_stage((it + 1) & 1, (it + 1) << 4);
            asm volatile("cp.async.wait_group 1;");
        } else {
            asm volatile("cp.async.wait_group 0;");
        }
        __syncthreads();

        const float* as_ = Asm[it & 1];
        const float* bs_ = Bsm[it & 1];

#pragma unroll
        for (int ks = 0; ks < 2; ks++) {
            const int kk = ks * 8;
            uint32_t af[4][4], bf[8][2];
#pragma unroll
            for (int i = 0; i < 4; i++) {
                int m = wm + i * 16 + g;
                af[i][0] = f2tf(as_[(size_t)m * 20 + kk + tig]);
                af[i][1] = f2tf(as_[(size_t)(m + 8) * 20 + kk + tig]);
                af[i][2] = f2tf(as_[(size_t)m * 20 + kk + tig + 4]);
                af[i][3] = f2tf(as_[(size_t)(m + 8) * 20 + kk + tig + 4]);
            }
#pragma unroll
            for (int j = 0; j < 8; j++) {
                int n = wn + j * 8 + g;
                if (TRANSB) {
                    bf[j][0] = f2tf(bs_[(size_t)n * 20 + kk + tig]);
                    bf[j][1] = f2tf(bs_[(size_t)n * 20 + kk + tig + 4]);
                } else {
                    bf[j][0] = f2tf(bs_[(size_t)(kk + tig) * 136 + n]);
                    bf[j][1] = f2tf(bs_[(size_t)(kk + tig + 4) * 136 + n]);
                }
            }
#pragma unroll
            for (int i = 0; i < 4; i++)
#pragma unroll
                for (int j = 0; j < 8; j++) {
                    asm volatile(
                        "mma.sync.aligned.m16n8k8.row.col.f32.tf32.tf32.f32 "
                        "{%0,%1,%2,%3}, {%4,%5,%6,%7}, {%8,%9}, {%0,%1,%2,%3};"
                        : "+f"(c[i][j][0]), "+f"(c[i][j][1]),
                          "+f"(c[i][j][2]), "+f"(c[i][j][3])
                        : "r"(af[i][0]), "r"(af[i][1]), "r"(af[i][2]), "r"(af[i][3]),
                          "r"(bf[j][0]), "r"(bf[j][1]));
                }
        }
        __syncthreads();
    }

    // ---- epilogue ----
#pragma unroll
    for (int i = 0; i < 4; i++) {
        int r0 = row0 + wm + i * 16 + g;
        int r1 = r0 + 8;
        float inv0 = 1.f, inv1 = 1.f;
        if (MODE == 3) {
            if (r0 < M) inv0 = 1.f / (aux[r0] + 1e-16f);
            if (r1 < M) inv1 = 1.f / (aux[r1] + 1e-16f);
        }
        float p0 = 0.f, p1 = 0.f;
#pragma unroll
        for (int j = 0; j < 8; j++) {
            int cc = col0 + wn + j * 8 + tig * 2;
            float v0 = c[i][j][0], v1 = c[i][j][1];
            float v2 = c[i][j][2], v3 = c[i][j][3];
            if (MODE == 1) {
                float bb0 = aux[cc], bb1 = aux[cc + 1];
                v0 = fmaxf(v0 + bb0, 0.f); v1 = fmaxf(v1 + bb1, 0.f);
                v2 = fmaxf(v2 + bb0, 0.f); v3 = fmaxf(v3 + bb1, 0.f);
            }
            if (MODE == 2) {
                v0 = __expf(v0); v1 = __expf(v1);
                v2 = __expf(v2); v3 = __expf(v3);
                p0 += v0 + v1; p1 += v2 + v3;
            }
            if (MODE == 3) {
                v0 *= inv0; v1 *= inv0; v2 *= inv1; v3 *= inv1;
            }
            if (r0 < M) *(float2*)(C + (size_t)r0 * N + cc) = make_float2(v0, v1);
            if (r1 < M) *(float2*)(C + (size_t)r1 * N + cc) = make_float2(v2, v3);
        }
        if (MODE == 2) {
            // quad reduce (lanes 4g..4g+3 share rows r0/r1)
            p0 += __shfl_down_sync(0xffffffffu, p0, 1);
            p0 += __shfl_down_sync(0xffffffffu, p0, 2);
            p1 += __shfl_down_sync(0xffffffffu, p1, 1);
            p1 += __shfl_down_sync(0xffffffffu, p1, 2);
            if (tig == 0) {
                if (r0 < M) atomicAdd(&rowsum[r0], p0);
                if (r1 < M) atomicAdd(&rowsum[r1], p1);
            }
        }
    }
}

// ---------------- misc small kernels ---------------------------------------
__global__ void k_zero(float* __restrict__ p, int n)
{
    int i = blockIdx.x * blockDim.x + threadIdx.x;
    if (i < n) p[i] = 0.f;
}

__global__ void k_gather_emb(const float* __restrict__ table, const int* __restrict__ idx,
                             float* __restrict__ out, int N)
{
    int i = blockIdx.x * blockDim.x + threadIdx.x;
    int total = N * DD;
    for (; i < total; i += gridDim.x * blockDim.x) {
        int n = i / DD, c = i - n * DD;
        out[i] = table[(size_t)idx[n] * DD + c];
    }
}

__global__ void k_scores(const float* __restrict__ h, const float* __restrict__ a_src,
                         const float* __restrict__ a_dst,
                         float* __restrict__ ssrc, float* __restrict__ sdst, int N)
{
    int n = blockIdx.x;
    int tid = threadIdx.x;        // 128
    int hh = tid >> 5, lane = tid & 31;
    const float* hr = h + (size_t)n * HD + hh * DD;
    float s1 = 0.f, s2 = 0.f;
    for (int c = lane; c < DD; c += 32) {
        float v = hr[c];
        s1 += v * a_src[hh * DD + c];
        s2 += v * a_dst[hh * DD + c];
    }
#pragma unroll
    for (int o = 16; o > 0; o >>= 1) {
        s1 += __shfl_down_sync(0xffffffffu, s1, o);
        s2 += __shfl_down_sync(0xffffffffu, s2, o);
    }
    if (lane == 0) { ssrc[n * HEADS + hh] = s1; sdst[n * HEADS + hh] = s2; }
}

__global__ void k_set_deg1(int* deg, int N)
{
    int i = blockIdx.x * blockDim.x + threadIdx.x;
    if (i < N) deg[i] = 1;
}
__global__ void k_count(const int* __restrict__ dst, int* __restrict__ deg, int E)
{
    int i = blockIdx.x * blockDim.x + threadIdx.x;
    for (; i < E; i += gridDim.x * blockDim.x) atomicAdd(&deg[dst[i]], 1);
}

// warp-shuffle based exclusive scan, 1024 threads, chunked
__global__ void k_exscan(const int* __restrict__ deg, int* __restrict__ off,
                         int* __restrict__ cur, int N)
{
    __shared__ int wsum[32];
    __shared__ int carry_s;
    int tid = threadIdx.x, lane = tid & 31, w = tid >> 5;
    if (tid == 0) carry_s = 0;
    __syncthreads();
    for (int base = 0; base < N; base += 1024) {
        int i = base + tid;
        int v = (i < N) ? deg[i] : 0;
        int x = v;
#pragma unroll
        for (int o = 1; o < 32; o <<= 1) {
            int t = __shfl_up_sync(0xffffffffu, x, o);
            if (lane >= o) x += t;
        }
        if (lane == 31) wsum[w] = x;
        __syncthreads();
        if (w == 0) {
            int s = wsum[lane];
#pragma unroll
            for (int o = 1; o < 32; o <<= 1) {
                int t = __shfl_up_sync(0xffffffffu, s, o);
                if (lane >= o) s += t;
            }
            wsum[lane] = s;
        }
        __syncthreads();
        int excl = carry_s + (w > 0 ? wsum[w - 1] : 0) + x - v;
        if (i < N) { off[i] = excl; cur[i] = excl; }
        __syncthreads();
        if (tid == 0) carry_s += wsum[31];
        __syncthreads();
    }
    if (tid == 0) off[N] = carry_s;
}
__global__ void k_fill(const int* __restrict__ src, const int* __restrict__ dst,
                       int* __restrict__ cur, int* __restrict__ csr, int E)
{
    int i = blockIdx.x * blockDim.x + threadIdx.x;
    for (; i < E; i += gridDim.x * blockDim.x) {
        int p = atomicAdd(&cur[dst[i]], 1);
        csr[p] = src[i];
    }
}
__global__ void k_fill_self(int* __restrict__ cur, int* __restrict__ csr, int N)
{
    int i = blockIdx.x * blockDim.x + threadIdx.x;
    if (i < N) { int p = atomicAdd(&cur[i], 1); csr[p] = i; }
}

// ---------------- GAT aggregation: one block per destination node ----------
#define AGG_CHUNK 512
__global__ void k_gat_agg(const float* __restrict__ h,      // [N, HD]
                          const float* __restrict__ ssrc,   // [N, 4]
                          const float* __restrict__ sdst,   // [N, 4]
                          const int* __restrict__ off, const int* __restrict__ csr,
                          const float* __restrict__ bias,   // [256]
                          float* __restrict__ out, int N)   // [N, 256]
{
    const int n = blockIdx.x;
    const int tid = threadIdx.x;      // 256
    const int e0 = off[n], e1 = off[n + 1];

    __shared__ int    s_src[AGG_CHUNK];
    __shared__ float  s_w[AGG_CHUNK * 4];
    __shared__ float4 red[256];
    __shared__ float  s_m[4], s_s[4];
    __shared__ float  s_out[1024];

    float sd[4];
#pragma unroll
    for (int hh = 0; hh < 4; hh++) sd[hh] = sdst[n * 4 + hh];

    float mloc[4] = {-1e30f, -1e30f, -1e30f, -1e30f};
    for (int e = e0 + tid; e < e1; e += 256) {
        int s = csr[e];
#pragma unroll
        for (int hh = 0; hh < 4; hh++) {
            float v = ssrc[s * 4 + hh] + sd[hh];
            v = v > 0.f ? v : 0.2f * v;
            mloc[hh] = fmaxf(mloc[hh], v);
        }
    }
    red[tid] = make_float4(mloc[0], mloc[1], mloc[2], mloc[3]);
    __syncthreads();
    for (int s = 128; s > 0; s >>= 1) {
        if (tid < s) {
            float4 a = red[tid], b = red[tid + s];
            a.x = fmaxf(a.x, b.x); a.y = fmaxf(a.y, b.y);
            a.z = fmaxf(a.z, b.z); a.w = fmaxf(a.w, b.w);
            red[tid] = a;
        }
        __syncthreads();
    }
    if (tid < 4) s_m[tid] = ((float*)&red[0])[tid];
    __syncthreads();
    float m0 = s_m[0], m1 = s_m[1], m2 = s_m[2], m3 = s_m[3];

    const int hh_ = tid >> 6;
    const int cb  = tid & 63;
    float acc0 = 0.f, acc1 = 0.f, acc2 = 0.f, acc3 = 0.f;
    float wsum[4] = {0.f, 0.f, 0.f, 0.f};

    for (int c0 = e0; c0 < e1; c0 += AGG_CHUNK) {
        int cnt = min(AGG_CHUNK, e1 - c0);
        for (int j = tid; j < cnt; j += 256) {
            int s = csr[c0 + j];
            s_src[j] = s;
            float v0 = ssrc[s * 4 + 0] + sd[0]; v0 = v0 > 0.f ? v0 : 0.2f * v0;
            float v1 = ssrc[s * 4 + 1] + sd[1]; v1 = v1 > 0.f ? v1 : 0.2f * v1;
            float v2 = ssrc[s * 4 + 2] + sd[2]; v2 = v2 > 0.f ? v2 : 0.2f * v2;
            float v3 = ssrc[s * 4 + 3] + sd[3]; v3 = v3 > 0.f ? v3 : 0.2f * v3;
            float w0 = __expf(v0 - m0), w1 = __expf(v1 - m1);
            float w2 = __expf(v2 - m2), w3 = __expf(v3 - m3);
            s_w[j * 4 + 0] = w0; s_w[j * 4 + 1] = w1;
            s_w[j * 4 + 2] = w2; s_w[j * 4 + 3] = w3;
            wsum[0] += w0; wsum[1] += w1; wsum[2] += w2; wsum[3] += w3;
        }
        __syncthreads();
        for (int j = 0; j < cnt; j++) {
            int s = s_src[j];
            float w = s_w[j * 4 + hh_];
            const float* hr = h + (size_t)s * HD + hh_ * DD + cb;
            acc0 += w * hr[0];
            acc1 += w * hr[64];
            acc2 += w * hr[128];
            acc3 += w * hr[192];
        }
        __syncthreads();
    }

    red[tid] = make_float4(wsum[0], wsum[1], wsum[2], wsum[3]);
    __syncthreads();
    for (int s = 128; s > 0; s >>= 1) {
        if (tid < s) {
            float4 a = red[tid], b = red[tid + s];
            a.x += b.x; a.y += b.y; a.z += b.z; a.w += b.w;
            red[tid] = a;
        }
        __syncthreads();
    }
    if (tid < 4) s_s[tid] = ((float*)&red[0])[tid];

    s_out[hh_ * 256 + cb]       = acc0;
    s_out[hh_ * 256 + cb + 64]  = acc1;
    s_out[hh_ * 256 + cb + 128] = acc2;
    s_out[hh_ * 256 + cb + 192] = acc3;
    __syncthreads();

    {
        int c = tid;
        float r = 0.f;
#pragma unroll
        for (int hh = 0; hh < 4; hh++)
            r += s_out[hh * 256 + c] / (s_s[hh] + 1e-16f);
        out[(size_t)n * DD + c] = 0.25f * r + bias[c];
    }
}

// ---------------- fused concat + final FC ([768] -> 32) --------------------
__global__ void k_final(const float* __restrict__ d, const float* __restrict__ ai,
                        const float* __restrict__ ae, const float* __restrict__ W,
                        const float* __restrict__ b, float* __restrict__ out, int M)
{
    __shared__ float s_in[8][768];
    int r0 = blockIdx.x * 8;
    int tid = threadIdx.x;   // 256
    for (int idx = tid; idx < 8 * 768; idx += 256) {
        int rr = idx / 768, cc = idx - rr * 768;
        int r = r0 + rr;
        float v = 0.f;
        if (r < M) {
            if (cc < 256)      v = d [(size_t)r * 256 + cc];
            else if (cc < 512) v = ai[(size_t)r * 256 + cc - 256];
            else               v = ae[(size_t)r * 256 + cc - 512];
        }
        s_in[rr][cc] = v;
    }
    __syncthreads();
    int rr = tid >> 5, j = tid & 31;
    int r = r0 + rr;
    if (r < M) {
        float acc = b[j];
#pragma unroll 8
        for (int k = 0; k < 768; k++) acc += s_in[rr][k] * W[k * 32 + j];
        out[(size_t)r * 32 + j] = acc;
    }
}

// ---------------- host orchestration ---------------------------------------
enum { GM_PLAIN = 0, GM_BIASRELU = 1, GM_EXPSUM = 2, GM_NORM = 3 };

static inline void launch_gemm(const float* A, const float* B, float* C,
                               const float* aux, float* rowsum,
                               int M, int N, int K, bool transb, int mode)
{
    dim3 grid(N / 128, (M + 255) / 256);
    if (transb) {
        cudaFuncSetAttribute(tgemm<true, GM_EXPSUM>, cudaFuncAttributeMaxDynamicSharedMemorySize, TG_SMEM);
        tgemm<true, GM_EXPSUM><<<grid, 256, TG_SMEM>>>(A, B, C, aux, rowsum, M, N, K);
    } else if (mode == GM_BIASRELU) {
        cudaFuncSetAttribute(tgemm<false, GM_BIASRELU>, cudaFuncAttributeMaxDynamicSharedMemorySize, TG_SMEM);
        tgemm<false, GM_BIASRELU><<<grid, 256, TG_SMEM>>>(A, B, C, aux, rowsum, M, N, K);
    } else if (mode == GM_NORM) {
        cudaFuncSetAttribute(tgemm<false, GM_NORM>, cudaFuncAttributeMaxDynamicSharedMemorySize, TG_SMEM);
        tgemm<false, GM_NORM><<<grid, 256, TG_SMEM>>>(A, B, C, aux, rowsum, M, N, K);
    } else {
        cudaFuncSetAttribute(tgemm<false, GM_PLAIN>, cudaFuncAttributeMaxDynamicSharedMemorySize, TG_SMEM);
        tgemm<false, GM_PLAIN><<<grid, 256, TG_SMEM>>>(A, B, C, aux, rowsum, M, N, K);
    }
}

struct Ptrs {
    float *hd, *hi, *he, *ie, *ee, *ssrc, *sdst, *ssum, *gat, *dd, *ii, *ev, *S, *atti, *atte;
    int *deg, *off, *cur, *csr;
};

static void run_gat(const float* x, const float* W, const float* a_src,
                    const float* a_dst, const float* bias,
                    const int* esrc, const int* edst,
                    int N, int E, int Din, float* hbuf, float* gat_out, const Ptrs& p)
{
    launch_gemm(x, W, hbuf, nullptr, nullptr, N, HD, Din, false, GM_PLAIN);
    k_scores<<<N, 128>>>(hbuf, a_src, a_dst, p.ssrc, p.sdst, N);
    k_set_deg1<<<(N + 255) / 256, 256>>>(p.deg, N);
    k_count<<<(E + 255) / 256 > 2048 ? 2048 : (E + 255) / 256, 256>>>(edst, p.deg, E);
    k_exscan<<<1, 1024>>>(p.deg, p.off, p.cur, N);
    k_fill<<<(E + 255) / 256 > 2048 ? 2048 : (E + 255) / 256, 256>>>(esrc, edst, p.cur, p.csr, E);
    k_fill_self<<<(N + 255) / 256, 256>>>(p.cur, p.csr, N);
    k_gat_agg<<<N, 256>>>(hbuf, p.ssrc, p.sdst, p.off, p.csr, bias, gat_out, N);
}

extern "C" void kernel_launch(void* const* d_in, const int* in_sizes, int n_in,
                              void* d_out, int out_size)
{
    const float* x_d     = (const float*)d_in[0];
    const int*   idx_i   = (const int*)  d_in[1];
    const int*   idx_e   = (const int*)  d_in[2];
    const int*   eidx_d  = (const int*)  d_in[3];
    const int*   eidx_i  = (const int*)  d_in[4];
    const int*   eidx_e  = (const int*)  d_in[5];
    const float* emb_i   = (const float*)d_in[6];
    const float* emb_e   = (const float*)d_in[7];
    const float* Wd      = (const float*)d_in[8];
    const float* a_src_d = (const float*)d_in[9];
    const float* a_dst_d = (const float*)d_in[10];
    const float* bd      = (const float*)d_in[11];
    const float* Wi      = (const float*)d_in[12];
    const float* a_src_i = (const float*)d_in[13];
    const float* a_dst_i = (const float*)d_in[14];
    const float* bi      = (const float*)d_in[15];
    const float* We      = (const float*)d_in[16];
    const float* a_src_e = (const float*)d_in[17];
    const float* a_dst_e = (const float*)d_in[18];
    const float* be      = (const float*)d_in[19];
    const float* W_dfc   = (const float*)d_in[20];
    const float* b_dfc   = (const float*)d_in[21];
    const float* W_ifc   = (const float*)d_in[22];
    const float* b_ifc   = (const float*)d_in[23];
    const float* W_efc   = (const float*)d_in[24];
    const float* b_efc   = (const float*)d_in[25];
    const float* W_fc    = (const float*)d_in[26];
    const float* b_fc    = (const float*)d_in[27];
    float* out = (float*)d_out;

    const int Din = 512;
    const int Nd = in_sizes[0] / Din;
    const int Ni = in_sizes[1];
    const int Ne = in_sizes[2];
    const int Ed = in_sizes[3] / 2;
    const int Ei = in_sizes[4] / 2;
    const int Ee = in_sizes[5] / 2;

    Ptrs p;
    cudaGetSymbolAddress((void**)&p.hd,   g_hd);
    cudaGetSymbolAddress((void**)&p.hi,   g_hi);
    cudaGetSymbolAddress((void**)&p.he,   g_he);
    cudaGetSymbolAddress((void**)&p.ie,   g_ie);
    cudaGetSymbolAddress((void**)&p.ee,   g_ee);
    cudaGetSymbolAddress((void**)&p.ssrc, g_ssrc);
    cudaGetSymbolAddress((void**)&p.sdst, g_sdst);
    cudaGetSymbolAddress((void**)&p.ssum, g_ssum);
    cudaGetSymbolAddress((void**)&p.gat,  g_gat);
    cudaGetSymbolAddress((void**)&p.dd,   g_dd);
    cudaGetSymbolAddress((void**)&p.ii,   g_ii);
    cudaGetSymbolAddress((void**)&p.ev,   g_ev);
    cudaGetSymbolAddress((void**)&p.S,    g_S);
    cudaGetSymbolAddress((void**)&p.atti, g_atti);
    cudaGetSymbolAddress((void**)&p.atte, g_atte);
    cudaGetSymbolAddress((void**)&p.deg,  g_deg);
    cudaGetSymbolAddress((void**)&p.off,  g_off);
    cudaGetSymbolAddress((void**)&p.cur,  g_cur);
    cudaGetSymbolAddress((void**)&p.csr,  g_csr);

    // embedding lookups
    k_gather_emb<<<2048, 256>>>(emb_i, idx_i, p.ie, Ni);
    k_gather_emb<<<2048, 256>>>(emb_e, idx_e, p.ee, Ne);

    // dialogue branch: GAT + relu FC
    run_gat(x_d, Wd, a_src_d, a_dst_d, bd, eidx_d, eidx_d + Ed, Nd, Ed, Din, p.hd, p.gat, p);
    launch_gemm(p.gat, W_dfc, p.dd, b_dfc, nullptr, Nd, DD, DD, false, GM_BIASRELU);

    // intention branch
    run_gat(p.ie, Wi, a_src_i, a_dst_i, bi, eidx_i, eidx_i + Ei, Ni, Ei, DD, p.hi, p.gat, p);
    launch_gemm(p.gat, W_ifc, p.ii, b_ifc, nullptr, Ni, DD, DD, false, GM_BIASRELU);

    // emotion branch
    run_gat(p.ee, We, a_src_e, a_dst_e, be, eidx_e, eidx_e + Ee, Ne, Ee, DD, p.he, p.gat, p);
    launch_gemm(p.gat, W_efc, p.ev, b_efc, nullptr, Ne, DD, DD, false, GM_BIASRELU);

    // cross attention: att_i = softmax(d @ i^T) @ i   (softmax fused into GEMMs)
    k_zero<<<(Nd + 255) / 256, 256>>>(p.ssum, Nd);
    launch_gemm(p.dd, p.ii, p.S, nullptr, p.ssum, Nd, Ni, DD, true, GM_EXPSUM);
    launch_gemm(p.S, p.ii, p.atti, p.ssum, nullptr, Nd, DD, Ni, false, GM_NORM);

    // att_e = softmax(d @ e^T) @ e
    k_zero<<<(Nd + 255) / 256, 256>>>(p.ssum, Nd);
    launch_gemm(p.dd, p.ev, p.S, nullptr, p.ssum, Nd, Ne, DD, true, GM_EXPSUM);
    launch_gemm(p.S, p.ev, p.atte, p.ssum, nullptr, Nd, DD, Ne, false, GM_NORM);

    // fused concat + final FC
    k_final<<<(Nd + 7) / 8, 256>>>(p.dd, p.atti, p.atte, W_fc, b_fc, out, Nd);
}

// round 5
// speedup vs baseline: 1.2610x; 1.2610x over previous
#include <cuda_runtime.h>
#include <math.h>
#include <stdint.h>

#define HEADS 4
#define DD 256
#define HD 1024            // HEADS * DD

#define MAXND 20000
#define MAXNI 4096
#define MAXED 640000
#define MAXET (MAXED + MAXND)

// ---------------- scratch (device globals; no allocation allowed) ----------
__device__ float g_hd  [(size_t)MAXND * HD];
__device__ float g_hi  [(size_t)MAXNI * HD];
__device__ float g_he  [(size_t)MAXNI * HD];
__device__ float g_ie  [(size_t)MAXNI * DD];
__device__ float g_ee  [(size_t)MAXNI * DD];
__device__ float g_ssrc[(size_t)MAXND * HEADS];
__device__ float g_sdst[(size_t)MAXND * HEADS];
__device__ float g_ssum[MAXND];                  // attention row sums
__device__ int   g_deg [MAXND];
__device__ int   g_off [MAXND + 1];
__device__ int   g_cur [MAXND];
__device__ int   g_csr [MAXET];
__device__ float g_gat [(size_t)MAXND * DD];
__device__ float g_dd  [(size_t)MAXND * DD];
__device__ float g_ii  [(size_t)MAXNI * DD];
__device__ float g_ev  [(size_t)MAXNI * DD];
__device__ float g_S   [(size_t)MAXND * 4096];
__device__ float g_atti[(size_t)MAXND * DD];
__device__ float g_atte[(size_t)MAXND * DD];

// ---------------- helpers ---------------------------------------------------
__device__ __forceinline__ uint32_t f2tf(float f) {
    uint32_t u;
    asm("cvt.rna.tf32.f32 %0, %1;" : "=r"(u) : "f"(f));
    return u;
}
__device__ __forceinline__ uint32_t smem_u32(const void* p) {
    uint32_t a;
    asm("{ .reg .u64 t; cvta.to.shared.u64 t, %1; cvt.u32.u64 %0, t; }"
        : "=r"(a) : "l"(p));
    return a;
}
#define CPASYNC16(d, s, sz) \
    asm volatile("cp.async.cg.shared.global [%0], [%1], 16, %2;" \
                 :: "r"(d), "l"(s), "r"(sz))
#define CPCOMMIT() asm volatile("cp.async.commit_group;")

// ---------------- tf32 tensor-core GEMM, cp.async 2-stage pipeline ----------
// C[M,N] = A[M,K] @ B  (B: [K,N] row-major; [N,K] row-major if TRANSB)
// BM=BN=128, BK=16, 256 threads = 8 warps (4x2), warp tile 32x64 (m16n8k8).
// MODE: 0 plain, 1 bias+relu, 2 exp + rowsum atomics, 3 divide by rowsum.
// Requires K % 16 == 0, N % 128 == 0; M guarded.
template<bool TRANSB, int MODE>
__global__ __launch_bounds__(256)
void tgemm(const float* __restrict__ A, const float* __restrict__ B,
           float* __restrict__ C, const float* __restrict__ aux,
           float* __restrict__ rowsum, int M, int N, int K)
{
    __shared__ float As[2][128 * 20];
    __shared__ float Bs[2][2560];      // NN uses 16*136=2176, TB uses 128*20=2560

    const int tid  = threadIdx.x;
    const int warp = tid >> 5, lane = tid & 31;
    const int g    = lane >> 2, tig = lane & 3;
    const int wm   = (warp >> 1) * 32;
    const int wn   = (warp & 1) * 64;
    const int row0 = blockIdx.y * 128, col0 = blockIdx.x * 128;

    float c[2][8][4];
#pragma unroll
    for (int i = 0; i < 2; i++)
#pragma unroll
        for (int j = 0; j < 8; j++)
#pragma unroll
            for (int q = 0; q < 4; q++) c[i][j][q] = 0.f;

    uint32_t asb[2], bsb[2];
    asb[0] = smem_u32(&As[0][0]); asb[1] = smem_u32(&As[1][0]);
    bsb[0] = smem_u32(&Bs[0][0]); bsb[1] = smem_u32(&Bs[1][0]);

    const int nIter = K >> 4;

    auto load_stage = [&](int s, int k0) {
#pragma unroll
        for (int i = 0; i < 2; i++) {        // A: 128 rows x 16 k = 512 chunks
            int f = tid + 256 * i;
            int row = f >> 2, c4 = (f & 3) * 4;
            int gr = row0 + row;
            const float* src = A + (size_t)(gr < M ? gr : M - 1) * K + k0 + c4;
            CPASYNC16(asb[s] + (row * 20 + c4) * 4, src, (gr < M) ? 16 : 0);
        }
#pragma unroll
        for (int i = 0; i < 2; i++) {        // B: 512 chunks
            int f = tid + 256 * i;
            if (TRANSB) {
                int n = f >> 2, k4 = (f & 3) * 4;
                const float* src = B + (size_t)(col0 + n) * K + k0 + k4;
                CPASYNC16(bsb[s] + (n * 20 + k4) * 4, src, 16);
            } else {
                int k = f >> 5, n4 = (f & 31) * 4;
                const float* src = B + (size_t)(k0 + k) * N + col0 + n4;
                CPASYNC16(bsb[s] + (k * 136 + n4) * 4, src, 16);
            }
        }
        CPCOMMIT();
    };

    load_stage(0, 0);

    for (int it = 0; it < nIter; it++) {
        if (it + 1 < nIter) {
            load_stage((it + 1) & 1, (it + 1) << 4);
            asm volatile("cp.async.wait_group 1;");
        } else {
            asm volatile("cp.async.wait_group 0;");
        }
        __syncthreads();

        const float* as_ = As[it & 1];
        const float* bs_ = Bs[it & 1];

#pragma unroll
        for (int ks = 0; ks < 2; ks++) {
            const int kk = ks * 8;
            uint32_t af[2][4], bf[8][2];
#pragma unroll
            for (int i = 0; i < 2; i++) {
                int m = wm + i * 16 + g;
                af[i][0] = f2tf(as_[(size_t)m * 20 + kk + tig]);
                af[i][1] = f2tf(as_[(size_t)(m + 8) * 20 + kk + tig]);
                af[i][2] = f2tf(as_[(size_t)m * 20 + kk + tig + 4]);
                af[i][3] = f2tf(as_[(size_t)(m + 8) * 20 + kk + tig + 4]);
            }
#pragma unroll
            for (int j = 0; j < 8; j++) {
                int n = wn + j * 8 + g;
                if (TRANSB) {
                    bf[j][0] = f2tf(bs_[(size_t)n * 20 + kk + tig]);
                    bf[j][1] = f2tf(bs_[(size_t)n * 20 + kk + tig + 4]);
                } else {
                    bf[j][0] = f2tf(bs_[(size_t)(kk + tig) * 136 + n]);
                    bf[j][1] = f2tf(bs_[(size_t)(kk + tig + 4) * 136 + n]);
                }
            }
#pragma unroll
            for (int i = 0; i < 2; i++)
#pragma unroll
                for (int j = 0; j < 8; j++) {
                    asm volatile(
                        "mma.sync.aligned.m16n8k8.row.col.f32.tf32.tf32.f32 "
                        "{%0,%1,%2,%3}, {%4,%5,%6,%7}, {%8,%9}, {%0,%1,%2,%3};"
                        : "+f"(c[i][j][0]), "+f"(c[i][j][1]),
                          "+f"(c[i][j][2]), "+f"(c[i][j][3])
                        : "r"(af[i][0]), "r"(af[i][1]), "r"(af[i][2]), "r"(af[i][3]),
                          "r"(bf[j][0]), "r"(bf[j][1]));
                }
        }
        __syncthreads();
    }

    // ---- epilogue ----
#pragma unroll
    for (int i = 0; i < 2; i++) {
        int r0 = row0 + wm + i * 16 + g;
        int r1 = r0 + 8;
        float inv0 = 1.f, inv1 = 1.f;
        if (MODE == 3) {
            if (r0 < M) inv0 = 1.f / (aux[r0] + 1e-16f);
            if (r1 < M) inv1 = 1.f / (aux[r1] + 1e-16f);
        }
        float p0 = 0.f, p1 = 0.f;
#pragma unroll
        for (int j = 0; j < 8; j++) {
            int cc = col0 + wn + j * 8 + tig * 2;
            float v0 = c[i][j][0], v1 = c[i][j][1];
            float v2 = c[i][j][2], v3 = c[i][j][3];
            if (MODE == 1) {
                float bb0 = aux[cc], bb1 = aux[cc + 1];
                v0 = fmaxf(v0 + bb0, 0.f); v1 = fmaxf(v1 + bb1, 0.f);
                v2 = fmaxf(v2 + bb0, 0.f); v3 = fmaxf(v3 + bb1, 0.f);
            }
            if (MODE == 2) {
                v0 = __expf(v0); v1 = __expf(v1);
                v2 = __expf(v2); v3 = __expf(v3);
                p0 += v0 + v1; p1 += v2 + v3;
            }
            if (MODE == 3) {
                v0 *= inv0; v1 *= inv0; v2 *= inv1; v3 *= inv1;
            }
            if (r0 < M) *(float2*)(C + (size_t)r0 * N + cc) = make_float2(v0, v1);
            if (r1 < M) *(float2*)(C + (size_t)r1 * N + cc) = make_float2(v2, v3);
        }
        if (MODE == 2) {
            // quad reduce: lanes 4g..4g+3 hold partials of rows r0/r1
            p0 += __shfl_down_sync(0xffffffffu, p0, 1);
            p0 += __shfl_down_sync(0xffffffffu, p0, 2);
            p1 += __shfl_down_sync(0xffffffffu, p1, 1);
            p1 += __shfl_down_sync(0xffffffffu, p1, 2);
            if (tig == 0) {
                if (r0 < M) atomicAdd(&rowsum[r0], p0);
                if (r1 < M) atomicAdd(&rowsum[r1], p1);
            }
        }
    }
}

// ---------------- misc small kernels ---------------------------------------
__global__ void k_zero(float* __restrict__ p, int n)
{
    int i = blockIdx.x * blockDim.x + threadIdx.x;
    if (i < n) p[i] = 0.f;
}

__global__ void k_gather_emb(const float* __restrict__ table, const int* __restrict__ idx,
                             float* __restrict__ out, int N)
{
    int i = blockIdx.x * blockDim.x + threadIdx.x;
    int total = N * DD;
    for (; i < total; i += gridDim.x * blockDim.x) {
        int n = i / DD, c = i - n * DD;
        out[i] = table[(size_t)idx[n] * DD + c];
    }
}

__global__ void k_scores(const float* __restrict__ h, const float* __restrict__ a_src,
                         const float* __restrict__ a_dst,
                         float* __restrict__ ssrc, float* __restrict__ sdst, int N)
{
    int n = blockIdx.x;
    int tid = threadIdx.x;        // 128
    int hh = tid >> 5, lane = tid & 31;
    const float* hr = h + (size_t)n * HD + hh * DD;
    float s1 = 0.f, s2 = 0.f;
    for (int c = lane; c < DD; c += 32) {
        float v = hr[c];
        s1 += v * a_src[hh * DD + c];
        s2 += v * a_dst[hh * DD + c];
    }
#pragma unroll
    for (int o = 16; o > 0; o >>= 1) {
        s1 += __shfl_down_sync(0xffffffffu, s1, o);
        s2 += __shfl_down_sync(0xffffffffu, s2, o);
    }
    if (lane == 0) { ssrc[n * HEADS + hh] = s1; sdst[n * HEADS + hh] = s2; }
}

__global__ void k_set_deg1(int* deg, int N)
{
    int i = blockIdx.x * blockDim.x + threadIdx.x;
    if (i < N) deg[i] = 1;
}
__global__ void k_count(const int* __restrict__ dst, int* __restrict__ deg, int E)
{
    int i = blockIdx.x * blockDim.x + threadIdx.x;
    for (; i < E; i += gridDim.x * blockDim.x) atomicAdd(&deg[dst[i]], 1);
}

// warp-shuffle based exclusive scan, 1024 threads, chunked
__global__ void k_exscan(const int* __restrict__ deg, int* __restrict__ off,
                         int* __restrict__ cur, int N)
{
    __shared__ int wsum[32];
    __shared__ int carry_s;
    int tid = threadIdx.x, lane = tid & 31, w = tid >> 5;
    if (tid == 0) carry_s = 0;
    __syncthreads();
    for (int base = 0; base < N; base += 1024) {
        int i = base + tid;
        int v = (i < N) ? deg[i] : 0;
        int x = v;
#pragma unroll
        for (int o = 1; o < 32; o <<= 1) {
            int t = __shfl_up_sync(0xffffffffu, x, o);
            if (lane >= o) x += t;
        }
        if (lane == 31) wsum[w] = x;
        __syncthreads();
        if (w == 0) {
            int s = wsum[lane];
#pragma unroll
            for (int o = 1; o < 32; o <<= 1) {
                int t = __shfl_up_sync(0xffffffffu, s, o);
                if (lane >= o) s += t;
            }
            wsum[lane] = s;
        }
        __syncthreads();
        int excl = carry_s + (w > 0 ? wsum[w - 1] : 0) + x - v;
        if (i < N) { off[i] = excl; cur[i] = excl; }
        __syncthreads();
        if (tid == 0) carry_s += wsum[31];
        __syncthreads();
    }
    if (tid == 0) off[N] = carry_s;
}
__global__ void k_fill(const int* __restrict__ src, const int* __restrict__ dst,
                       int* __restrict__ cur, int* __restrict__ csr, int E)
{
    int i = blockIdx.x * blockDim.x + threadIdx.x;
    for (; i < E; i += gridDim.x * blockDim.x) {
        int p = atomicAdd(&cur[dst[i]], 1);
        csr[p] = src[i];
    }
}
__global__ void k_fill_self(int* __restrict__ cur, int* __restrict__ csr, int N)
{
    int i = blockIdx.x * blockDim.x + threadIdx.x;
    if (i < N) { int p = atomicAdd(&cur[i], 1); csr[p] = i; }
}

// ---------------- GAT aggregation: one block per destination node ----------
#define AGG_CHUNK 512
__global__ void k_gat_agg(const float* __restrict__ h,      // [N, HD]
                          const float* __restrict__ ssrc,   // [N, 4]
                          const float* __restrict__ sdst,   // [N, 4]
                          const int* __restrict__ off, const int* __restrict__ csr,
                          const float* __restrict__ bias,   // [256]
                          float* __restrict__ out, int N)   // [N, 256]
{
    const int n = blockIdx.x;
    const int tid = threadIdx.x;      // 256
    const int e0 = off[n], e1 = off[n + 1];

    __shared__ int    s_src[AGG_CHUNK];
    __shared__ float  s_w[AGG_CHUNK * 4];
    __shared__ float4 red[256];
    __shared__ float  s_m[4], s_s[4];
    __shared__ float  s_out[1024];

    float sd[4];
#pragma unroll
    for (int hh = 0; hh < 4; hh++) sd[hh] = sdst[n * 4 + hh];

    float mloc[4] = {-1e30f, -1e30f, -1e30f, -1e30f};
    for (int e = e0 + tid; e < e1; e += 256) {
        int s = csr[e];
#pragma unroll
        for (int hh = 0; hh < 4; hh++) {
            float v = ssrc[s * 4 + hh] + sd[hh];
            v = v > 0.f ? v : 0.2f * v;
            mloc[hh] = fmaxf(mloc[hh], v);
        }
    }
    red[tid] = make_float4(mloc[0], mloc[1], mloc[2], mloc[3]);
    __syncthreads();
    for (int s = 128; s > 0; s >>= 1) {
        if (tid < s) {
            float4 a = red[tid], b = red[tid + s];
            a.x = fmaxf(a.x, b.x); a.y = fmaxf(a.y, b.y);
            a.z = fmaxf(a.z, b.z); a.w = fmaxf(a.w, b.w);
            red[tid] = a;
        }
        __syncthreads();
    }
    if (tid < 4) s_m[tid] = ((float*)&red[0])[tid];
    __syncthreads();
    float m0 = s_m[0], m1 = s_m[1], m2 = s_m[2], m3 = s_m[3];

    const int hh_ = tid >> 6;
    const int cb  = tid & 63;
    float acc0 = 0.f, acc1 = 0.f, acc2 = 0.f, acc3 = 0.f;
    float wsum[4] = {0.f, 0.f, 0.f, 0.f};

    for (int c0 = e0; c0 < e1; c0 += AGG_CHUNK) {
        int cnt = min(AGG_CHUNK, e1 - c0);
        for (int j = tid; j < cnt; j += 256) {
            int s = csr[c0 + j];
            s_src[j] = s;
            float v0 = ssrc[s * 4 + 0] + sd[0]; v0 = v0 > 0.f ? v0 : 0.2f * v0;
            float v1 = ssrc[s * 4 + 1] + sd[1]; v1 = v1 > 0.f ? v1 : 0.2f * v1;
            float v2 = ssrc[s * 4 + 2] + sd[2]; v2 = v2 > 0.f ? v2 : 0.2f * v2;
            float v3 = ssrc[s * 4 + 3] + sd[3]; v3 = v3 > 0.f ? v3 : 0.2f * v3;
            float w0 = __expf(v0 - m0), w1 = __expf(v1 - m1);
            float w2 = __expf(v2 - m2), w3 = __expf(v3 - m3);
            s_w[j * 4 + 0] = w0; s_w[j * 4 + 1] = w1;
            s_w[j * 4 + 2] = w2; s_w[j * 4 + 3] = w3;
            wsum[0] += w0; wsum[1] += w1; wsum[2] += w2; wsum[3] += w3;
        }
        __syncthreads();
        for (int j = 0; j < cnt; j++) {
            int s = s_src[j];
            float w = s_w[j * 4 + hh_];
            const float* hr = h + (size_t)s * HD + hh_ * DD + cb;
            acc0 += w * hr[0];
            acc1 += w * hr[64];
            acc2 += w * hr[128];
            acc3 += w * hr[192];
        }
        __syncthreads();
    }

    red[tid] = make_float4(wsum[0], wsum[1], wsum[2], wsum[3]);
    __syncthreads();
    for (int s = 128; s > 0; s >>= 1) {
        if (tid < s) {
            float4 a = red[tid], b = red[tid + s];
            a.x += b.x; a.y += b.y; a.z += b.z; a.w += b.w;
            red[tid] = a;
        }
        __syncthreads();
    }
    if (tid < 4) s_s[tid] = ((float*)&red[0])[tid];

    s_out[hh_ * 256 + cb]       = acc0;
    s_out[hh_ * 256 + cb + 64]  = acc1;
    s_out[hh_ * 256 + cb + 128] = acc2;
    s_out[hh_ * 256 + cb + 192] = acc3;
    __syncthreads();

    {
        int c = tid;
        float r = 0.f;
#pragma unroll
        for (int hh = 0; hh < 4; hh++)
            r += s_out[hh * 256 + c] / (s_s[hh] + 1e-16f);
        out[(size_t)n * DD + c] = 0.25f * r + bias[c];
    }
}

// ---------------- fused concat + final FC ([768] -> 32) --------------------
__global__ void k_final(const float* __restrict__ d, const float* __restrict__ ai,
                        const float* __restrict__ ae, const float* __restrict__ W,
                        const float* __restrict__ b, float* __restrict__ out, int M)
{
    __shared__ float s_in[8][768];
    int r0 = blockIdx.x * 8;
    int tid = threadIdx.x;   // 256
    for (int idx = tid; idx < 8 * 768; idx += 256) {
        int rr = idx / 768, cc = idx - rr * 768;
        int r = r0 + rr;
        float v = 0.f;
        if (r < M) {
            if (cc < 256)      v = d [(size_t)r * 256 + cc];
            else if (cc < 512) v = ai[(size_t)r * 256 + cc - 256];
            else               v = ae[(size_t)r * 256 + cc - 512];
        }
        s_in[rr][cc] = v;
    }
    __syncthreads();
    int rr = tid >> 5, j = tid & 31;
    int r = r0 + rr;
    if (r < M) {
        float acc = b[j];
#pragma unroll 8
        for (int k = 0; k < 768; k++) acc += s_in[rr][k] * W[k * 32 + j];
        out[(size_t)r * 32 + j] = acc;
    }
}

// ---------------- host orchestration ---------------------------------------
enum { GM_PLAIN = 0, GM_BIASRELU = 1, GM_EXPSUM = 2, GM_NORM = 3 };

static inline void launch_gemm(const float* A, const float* B, float* C,
                               const float* aux, float* rowsum,
                               int M, int N, int K, bool transb, int mode)
{
    dim3 grid(N / 128, (M + 127) / 128);
    if (transb) {
        tgemm<true, GM_EXPSUM><<<grid, 256>>>(A, B, C, aux, rowsum, M, N, K);
    } else if (mode == GM_BIASRELU) {
        tgemm<false, GM_BIASRELU><<<grid, 256>>>(A, B, C, aux, rowsum, M, N, K);
    } else if (mode == GM_NORM) {
        tgemm<false, GM_NORM><<<grid, 256>>>(A, B, C, aux, rowsum, M, N, K);
    } else {
        tgemm<false, GM_PLAIN><<<grid, 256>>>(A, B, C, aux, rowsum, M, N, K);
    }
}

struct Ptrs {
    float *hd, *hi, *he, *ie, *ee, *ssrc, *sdst, *ssum, *gat, *dd, *ii, *ev, *S, *atti, *atte;
    int *deg, *off, *cur, *csr;
};

static void run_gat(const float* x, const float* W, const float* a_src,
                    const float* a_dst, const float* bias,
                    const int* esrc, const int* edst,
                    int N, int E, int Din, float* hbuf, float* gat_out, const Ptrs& p)
{
    launch_gemm(x, W, hbuf, nullptr, nullptr, N, HD, Din, false, GM_PLAIN);
    k_scores<<<N, 128>>>(hbuf, a_src, a_dst, p.ssrc, p.sdst, N);
    k_set_deg1<<<(N + 255) / 256, 256>>>(p.deg, N);
    k_count<<<(E + 255) / 256 > 2048 ? 2048 : (E + 255) / 256, 256>>>(edst, p.deg, E);
    k_exscan<<<1, 1024>>>(p.deg, p.off, p.cur, N);
    k_fill<<<(E + 255) / 256 > 2048 ? 2048 : (E + 255) / 256, 256>>>(esrc, edst, p.cur, p.csr, E);
    k_fill_self<<<(N + 255) / 256, 256>>>(p.cur, p.csr, N);
    k_gat_agg<<<N, 256>>>(hbuf, p.ssrc, p.sdst, p.off, p.csr, bias, gat_out, N);
}

extern "C" void kernel_launch(void* const* d_in, const int* in_sizes, int n_in,
                              void* d_out, int out_size)
{
    const float* x_d     = (const float*)d_in[0];
    const int*   idx_i   = (const int*)  d_in[1];
    const int*   idx_e   = (const int*)  d_in[2];
    const int*   eidx_d  = (const int*)  d_in[3];
    const int*   eidx_i  = (const int*)  d_in[4];
    const int*   eidx_e  = (const int*)  d_in[5];
    const float* emb_i   = (const float*)d_in[6];
    const float* emb_e   = (const float*)d_in[7];
    const float* Wd      = (const float*)d_in[8];
    const float* a_src_d = (const float*)d_in[9];
    const float* a_dst_d = (const float*)d_in[10];
    const float* bd      = (const float*)d_in[11];
    const float* Wi      = (const float*)d_in[12];
    const float* a_src_i = (const float*)d_in[13];
    const float* a_dst_i = (const float*)d_in[14];
    const float* bi      = (const float*)d_in[15];
    const float* We      = (const float*)d_in[16];
    const float* a_src_e = (const float*)d_in[17];
    const float* a_dst_e = (const float*)d_in[18];
    const float* be      = (const float*)d_in[19];
    const float* W_dfc   = (const float*)d_in[20];
    const float* b_dfc   = (const float*)d_in[21];
    const float* W_ifc   = (const float*)d_in[22];
    const float* b_ifc   = (const float*)d_in[23];
    const float* W_efc   = (const float*)d_in[24];
    const float* b_efc   = (const float*)d_in[25];
    const float* W_fc    = (const float*)d_in[26];
    const float* b_fc    = (const float*)d_in[27];
    float* out = (float*)d_out;

    const int Din = 512;
    const int Nd = in_sizes[0] / Din;
    const int Ni = in_sizes[1];
    const int Ne = in_sizes[2];
    const int Ed = in_sizes[3] / 2;
    const int Ei = in_sizes[4] / 2;
    const int Ee = in_sizes[5] / 2;

    Ptrs p;
    cudaGetSymbolAddress((void**)&p.hd,   g_hd);
    cudaGetSymbolAddress((void**)&p.hi,   g_hi);
    cudaGetSymbolAddress((void**)&p.he,   g_he);
    cudaGetSymbolAddress((void**)&p.ie,   g_ie);
    cudaGetSymbolAddress((void**)&p.ee,   g_ee);
    cudaGetSymbolAddress((void**)&p.ssrc, g_ssrc);
    cudaGetSymbolAddress((void**)&p.sdst, g_sdst);
    cudaGetSymbolAddress((void**)&p.ssum, g_ssum);
    cudaGetSymbolAddress((void**)&p.gat,  g_gat);
    cudaGetSymbolAddress((void**)&p.dd,   g_dd);
    cudaGetSymbolAddress((void**)&p.ii,   g_ii);
    cudaGetSymbolAddress((void**)&p.ev,   g_ev);
    cudaGetSymbolAddress((void**)&p.S,    g_S);
    cudaGetSymbolAddress((void**)&p.atti, g_atti);
    cudaGetSymbolAddress((void**)&p.atte, g_atte);
    cudaGetSymbolAddress((void**)&p.deg,  g_deg);
    cudaGetSymbolAddress((void**)&p.off,  g_off);
    cudaGetSymbolAddress((void**)&p.cur,  g_cur);
    cudaGetSymbolAddress((void**)&p.csr,  g_csr);

    // embedding lookups
    k_gather_emb<<<2048, 256>>>(emb_i, idx_i, p.ie, Ni);
    k_gather_emb<<<2048, 256>>>(emb_e, idx_e, p.ee, Ne);

    // dialogue branch: GAT + relu FC
    run_gat(x_d, Wd, a_src_d, a_dst_d, bd, eidx_d, eidx_d + Ed, Nd, Ed, Din, p.hd, p.gat, p);
    launch_gemm(p.gat, W_dfc, p.dd, b_dfc, nullptr, Nd, DD, DD, false, GM_BIASRELU);

    // intention branch
    run_gat(p.ie, Wi, a_src_i, a_dst_i, bi, eidx_i, eidx_i + Ei, Ni, Ei, DD, p.hi, p.gat, p);
    launch_gemm(p.gat, W_ifc, p.ii, b_ifc, nullptr, Ni, DD, DD, false, GM_BIASRELU);

    // emotion branch
    run_gat(p.ee, We, a_src_e, a_dst_e, be, eidx_e, eidx_e + Ee, Ne, Ee, DD, p.he, p.gat, p);
    launch_gemm(p.gat, W_efc, p.ev, b_efc, nullptr, Ne, DD, DD, false, GM_BIASRELU);

    // cross attention: att_i = softmax(d @ i^T) @ i   (softmax fused into GEMMs)
    k_zero<<<(Nd + 255) / 256, 256>>>(p.ssum, Nd);
    launch_gemm(p.dd, p.ii, p.S, nullptr, p.ssum, Nd, Ni, DD, true, GM_EXPSUM);
    launch_gemm(p.S, p.ii, p.atti, p.ssum, nullptr, Nd, DD, Ni, false, GM_NORM);

    // att_e = softmax(d @ e^T) @ e
    k_zero<<<(Nd + 255) / 256, 256>>>(p.ssum, Nd);
    launch_gemm(p.dd, p.ev, p.S, nullptr, p.ssum, Nd, Ne, DD, true, GM_EXPSUM);
    launch_gemm(p.S, p.ev, p.atte, p.ssum, nullptr, Nd, DD, Ne, false, GM_NORM);

    // fused concat + final FC
    k_final<<<(Nd + 7) / 8, 256>>>(p.dd, p.atti, p.atte, W_fc, b_fc, out, Nd);
}

// round 6
// speedup vs baseline: 1.3188x; 1.0458x over previous
#include <cuda_runtime.h>
#include <math.h>
#include <stdint.h>

#define HEADS 4
#define DD 256
#define HD 1024            // HEADS * DD

#define MAXND 20000
#define MAXNI 4096
#define MAXED 640000
#define MAXET (MAXED + MAXND)

// ---------------- scratch (device globals; no allocation allowed) ----------
__device__ float g_hd  [(size_t)MAXND * HD];
__device__ float g_hi  [(size_t)MAXNI * HD];
__device__ float g_he  [(size_t)MAXNI * HD];
__device__ float g_ie  [(size_t)MAXNI * DD];
__device__ float g_ee  [(size_t)MAXNI * DD];
__device__ float g_ssrc[(size_t)MAXND * HEADS];
__device__ float g_sdst[(size_t)MAXND * HEADS];
__device__ float g_ssum[MAXND];                  // attention row sums
__device__ int   g_deg [MAXND];
__device__ int   g_off [MAXND + 1];
__device__ int   g_cur [MAXND];
__device__ int   g_csr [MAXET];
__device__ float g_gat [(size_t)MAXND * DD];
__device__ float g_dd  [(size_t)MAXND * DD];
__device__ float g_ii  [(size_t)MAXNI * DD];
__device__ float g_ev  [(size_t)MAXNI * DD];
__device__ float g_S   [(size_t)MAXND * 4096];   // also reused as x_d tf32 scratch
__device__ float g_atti[(size_t)MAXND * DD];
__device__ float g_atte[(size_t)MAXND * DD];
__device__ float g_wtmp[512 * 1024];             // converted weight scratch

// ---------------- helpers ---------------------------------------------------
__device__ __forceinline__ uint32_t f2tf(float f) {
    uint32_t u;
    asm("cvt.rna.tf32.f32 %0, %1;" : "=r"(u) : "f"(f));
    return u;
}
__device__ __forceinline__ float f2tf_f(float f) {
    return __uint_as_float(f2tf(f));
}
__device__ __forceinline__ uint32_t smem_u32(const void* p) {
    uint32_t a;
    asm("{ .reg .u64 t; cvta.to.shared.u64 t, %1; cvt.u32.u64 %0, t; }"
        : "=r"(a) : "l"(p));
    return a;
}
#define CPASYNC16(d, s, sz) \
    asm volatile("cp.async.cg.shared.global [%0], [%1], 16, %2;" \
                 :: "r"(d), "l"(s), "r"(sz))
#define CPCOMMIT() asm volatile("cp.async.commit_group;")

// ---------------- tf32 tensor-core GEMM, cp.async 2-stage pipeline ----------
// All operands MUST already hold tf32-rounded bit patterns (no cvt in loop).
// C[M,N] = A[M,K] @ B  (B: [K,N] row-major; [N,K] row-major if TRANSB)
// BM=BN=128, BK=16, 256 threads = 8 warps (4x2), warp tile 32x64 (m16n8k8).
// MODE: 0 plain, 1 bias+relu (tf32-rounded out), 2 exp+rowsum (tf32 out),
//       3 divide by rowsum.
template<bool TRANSB, int MODE>
__global__ __launch_bounds__(256)
void tgemm(const float* __restrict__ A, const float* __restrict__ B,
           float* __restrict__ C, const float* __restrict__ aux,
           float* __restrict__ rowsum, int M, int N, int K)
{
    __shared__ float As[2][128 * 20];
    __shared__ float Bs[2][2560];      // NN uses 16*136=2176, TB uses 128*20=2560

    const int tid  = threadIdx.x;
    const int warp = tid >> 5, lane = tid & 31;
    const int g    = lane >> 2, tig = lane & 3;
    const int wm   = (warp >> 1) * 32;
    const int wn   = (warp & 1) * 64;
    const int row0 = blockIdx.y * 128, col0 = blockIdx.x * 128;

    float c[2][8][4];
#pragma unroll
    for (int i = 0; i < 2; i++)
#pragma unroll
        for (int j = 0; j < 8; j++)
#pragma unroll
            for (int q = 0; q < 4; q++) c[i][j][q] = 0.f;

    uint32_t asb[2], bsb[2];
    asb[0] = smem_u32(&As[0][0]); asb[1] = smem_u32(&As[1][0]);
    bsb[0] = smem_u32(&Bs[0][0]); bsb[1] = smem_u32(&Bs[1][0]);

    const int nIter = K >> 4;

    auto load_stage = [&](int s, int k0) {
#pragma unroll
        for (int i = 0; i < 2; i++) {        // A: 128 rows x 16 k = 512 chunks
            int f = tid + 256 * i;
            int row = f >> 2, c4 = (f & 3) * 4;
            int gr = row0 + row;
            const float* src = A + (size_t)(gr < M ? gr : M - 1) * K + k0 + c4;
            CPASYNC16(asb[s] + (row * 20 + c4) * 4, src, (gr < M) ? 16 : 0);
        }
#pragma unroll
        for (int i = 0; i < 2; i++) {        // B: 512 chunks
            int f = tid + 256 * i;
            if (TRANSB) {
                int n = f >> 2, k4 = (f & 3) * 4;
                const float* src = B + (size_t)(col0 + n) * K + k0 + k4;
                CPASYNC16(bsb[s] + (n * 20 + k4) * 4, src, 16);
            } else {
                int k = f >> 5, n4 = (f & 31) * 4;
                const float* src = B + (size_t)(k0 + k) * N + col0 + n4;
                CPASYNC16(bsb[s] + (k * 136 + n4) * 4, src, 16);
            }
        }
        CPCOMMIT();
    };

    load_stage(0, 0);

    for (int it = 0; it < nIter; it++) {
        if (it + 1 < nIter) {
            load_stage((it + 1) & 1, (it + 1) << 4);
            asm volatile("cp.async.wait_group 1;");
        } else {
            asm volatile("cp.async.wait_group 0;");
        }
        __syncthreads();

        const float* as_ = As[it & 1];
        const float* bs_ = Bs[it & 1];

#pragma unroll
        for (int ks = 0; ks < 2; ks++) {
            const int kk = ks * 8;
            uint32_t af[2][4], bf[8][2];
#pragma unroll
            for (int i = 0; i < 2; i++) {
                int m = wm + i * 16 + g;
                af[i][0] = __float_as_uint(as_[(size_t)m * 20 + kk + tig]);
                af[i][1] = __float_as_uint(as_[(size_t)(m + 8) * 20 + kk + tig]);
                af[i][2] = __float_as_uint(as_[(size_t)m * 20 + kk + tig + 4]);
                af[i][3] = __float_as_uint(as_[(size_t)(m + 8) * 20 + kk + tig + 4]);
            }
#pragma unroll
            for (int j = 0; j < 8; j++) {
                int n = wn + j * 8 + g;
                if (TRANSB) {
                    bf[j][0] = __float_as_uint(bs_[(size_t)n * 20 + kk + tig]);
                    bf[j][1] = __float_as_uint(bs_[(size_t)n * 20 + kk + tig + 4]);
                } else {
                    bf[j][0] = __float_as_uint(bs_[(size_t)(kk + tig) * 136 + n]);
                    bf[j][1] = __float_as_uint(bs_[(size_t)(kk + tig + 4) * 136 + n]);
                }
            }
#pragma unroll
            for (int i = 0; i < 2; i++)
#pragma unroll
                for (int j = 0; j < 8; j++) {
                    asm volatile(
                        "mma.sync.aligned.m16n8k8.row.col.f32.tf32.tf32.f32 "
                        "{%0,%1,%2,%3}, {%4,%5,%6,%7}, {%8,%9}, {%0,%1,%2,%3};"
                        : "+f"(c[i][j][0]), "+f"(c[i][j][1]),
                          "+f"(c[i][j][2]), "+f"(c[i][j][3])
                        : "r"(af[i][0]), "r"(af[i][1]), "r"(af[i][2]), "r"(af[i][3]),
                          "r"(bf[j][0]), "r"(bf[j][1]));
                }
        }
        __syncthreads();
    }

    // ---- epilogue ----
#pragma unroll
    for (int i = 0; i < 2; i++) {
        int r0 = row0 + wm + i * 16 + g;
        int r1 = r0 + 8;
        float inv0 = 1.f, inv1 = 1.f;
        if (MODE == 3) {
            if (r0 < M) inv0 = 1.f / (aux[r0] + 1e-16f);
            if (r1 < M) inv1 = 1.f / (aux[r1] + 1e-16f);
        }
        float p0 = 0.f, p1 = 0.f;
#pragma unroll
        for (int j = 0; j < 8; j++) {
            int cc = col0 + wn + j * 8 + tig * 2;
            float v0 = c[i][j][0], v1 = c[i][j][1];
            float v2 = c[i][j][2], v3 = c[i][j][3];
            if (MODE == 1) {
                float bb0 = aux[cc], bb1 = aux[cc + 1];
                v0 = f2tf_f(fmaxf(v0 + bb0, 0.f)); v1 = f2tf_f(fmaxf(v1 + bb1, 0.f));
                v2 = f2tf_f(fmaxf(v2 + bb0, 0.f)); v3 = f2tf_f(fmaxf(v3 + bb1, 0.f));
            }
            if (MODE == 2) {
                v0 = f2tf_f(__expf(v0)); v1 = f2tf_f(__expf(v1));
                v2 = f2tf_f(__expf(v2)); v3 = f2tf_f(__expf(v3));
                p0 += v0 + v1; p1 += v2 + v3;
            }
            if (MODE == 3) {
                v0 *= inv0; v1 *= inv0; v2 *= inv1; v3 *= inv1;
            }
            if (r0 < M) *(float2*)(C + (size_t)r0 * N + cc) = make_float2(v0, v1);
            if (r1 < M) *(float2*)(C + (size_t)r1 * N + cc) = make_float2(v2, v3);
        }
        if (MODE == 2) {
            // quad reduce: lanes 4g..4g+3 hold partials of rows r0/r1
            p0 += __shfl_down_sync(0xffffffffu, p0, 1);
            p0 += __shfl_down_sync(0xffffffffu, p0, 2);
            p1 += __shfl_down_sync(0xffffffffu, p1, 1);
            p1 += __shfl_down_sync(0xffffffffu, p1, 2);
            if (tig == 0) {
                if (r0 < M) atomicAdd(&rowsum[r0], p0);
                if (r1 < M) atomicAdd(&rowsum[r1], p1);
            }
        }
    }
}

// ---------------- misc small kernels ---------------------------------------
__global__ void k_zero(float* __restrict__ p, int n)
{
    int i = blockIdx.x * blockDim.x + threadIdx.x;
    if (i < n) p[i] = 0.f;
}

// elementwise tf32 rounding pass (for raw inputs used as GEMM operands)
__global__ void k_pretf(const float* __restrict__ in, float* __restrict__ out, int n)
{
    int i = blockIdx.x * blockDim.x + threadIdx.x;
    for (; i < n; i += gridDim.x * blockDim.x) out[i] = f2tf_f(in[i]);
}

__global__ void k_gather_emb(const float* __restrict__ table, const int* __restrict__ idx,
                             float* __restrict__ out, int N)
{
    int i = blockIdx.x * blockDim.x + threadIdx.x;
    int total = N * DD;
    for (; i < total; i += gridDim.x * blockDim.x) {
        int n = i / DD, c = i - n * DD;
        out[i] = f2tf_f(table[(size_t)idx[n] * DD + c]);
    }
}

__global__ void k_scores(const float* __restrict__ h, const float* __restrict__ a_src,
                         const float* __restrict__ a_dst,
                         float* __restrict__ ssrc, float* __restrict__ sdst, int N)
{
    int n = blockIdx.x;
    int tid = threadIdx.x;        // 128
    int hh = tid >> 5, lane = tid & 31;
    const float* hr = h + (size_t)n * HD + hh * DD;
    float s1 = 0.f, s2 = 0.f;
    for (int c = lane; c < DD; c += 32) {
        float v = hr[c];
        s1 += v * a_src[hh * DD + c];
        s2 += v * a_dst[hh * DD + c];
    }
#pragma unroll
    for (int o = 16; o > 0; o >>= 1) {
        s1 += __shfl_down_sync(0xffffffffu, s1, o);
        s2 += __shfl_down_sync(0xffffffffu, s2, o);
    }
    if (lane == 0) { ssrc[n * HEADS + hh] = s1; sdst[n * HEADS + hh] = s2; }
}

__global__ void k_set_deg1(int* deg, int N)
{
    int i = blockIdx.x * blockDim.x + threadIdx.x;
    if (i < N) deg[i] = 1;
}
__global__ void k_count(const int* __restrict__ dst, int* __restrict__ deg, int E)
{
    int i = blockIdx.x * blockDim.x + threadIdx.x;
    for (; i < E; i += gridDim.x * blockDim.x) atomicAdd(&deg[dst[i]], 1);
}

// warp-shuffle based exclusive scan, 1024 threads, chunked
__global__ void k_exscan(const int* __restrict__ deg, int* __restrict__ off,
                         int* __restrict__ cur, int N)
{
    __shared__ int wsum[32];
    __shared__ int carry_s;
    int tid = threadIdx.x, lane = tid & 31, w = tid >> 5;
    if (tid == 0) carry_s = 0;
    __syncthreads();
    for (int base = 0; base < N; base += 1024) {
        int i = base + tid;
        int v = (i < N) ? deg[i] : 0;
        int x = v;
#pragma unroll
        for (int o = 1; o < 32; o <<= 1) {
            int t = __shfl_up_sync(0xffffffffu, x, o);
            if (lane >= o) x += t;
        }
        if (lane == 31) wsum[w] = x;
        __syncthreads();
        if (w == 0) {
            int s = wsum[lane];
#pragma unroll
            for (int o = 1; o < 32; o <<= 1) {
                int t = __shfl_up_sync(0xffffffffu, s, o);
                if (lane >= o) s += t;
            }
            wsum[lane] = s;
        }
        __syncthreads();
        int excl = carry_s + (w > 0 ? wsum[w - 1] : 0) + x - v;
        if (i < N) { off[i] = excl; cur[i] = excl; }
        __syncthreads();
        if (tid == 0) carry_s += wsum[31];
        __syncthreads();
    }
    if (tid == 0) off[N] = carry_s;
}
__global__ void k_fill(const int* __restrict__ src, const int* __restrict__ dst,
                       int* __restrict__ cur, int* __restrict__ csr, int E)
{
    int i = blockIdx.x * blockDim.x + threadIdx.x;
    for (; i < E; i += gridDim.x * blockDim.x) {
        int p = atomicAdd(&cur[dst[i]], 1);
        csr[p] = src[i];
    }
}
__global__ void k_fill_self(int* __restrict__ cur, int* __restrict__ csr, int N)
{
    int i = blockIdx.x * blockDim.x + threadIdx.x;
    if (i < N) { int p = atomicAdd(&cur[i], 1); csr[p] = i; }
}

// ---------------- GAT aggregation: one block per destination node ----------
#define AGG_CHUNK 512
__global__ void k_gat_agg(const float* __restrict__ h,      // [N, HD]
                          const float* __restrict__ ssrc,   // [N, 4]
                          const float* __restrict__ sdst,   // [N, 4]
                          const int* __restrict__ off, const int* __restrict__ csr,
                          const float* __restrict__ bias,   // [256]
                          float* __restrict__ out, int N)   // [N, 256] (tf32-rounded)
{
    const int n = blockIdx.x;
    const int tid = threadIdx.x;      // 256
    const int e0 = off[n], e1 = off[n + 1];

    __shared__ int    s_src[AGG_CHUNK];
    __shared__ float  s_w[AGG_CHUNK * 4];
    __shared__ float4 red[256];
    __shared__ float  s_m[4], s_s[4];
    __shared__ float  s_out[1024];

    float sd[4];
#pragma unroll
    for (int hh = 0; hh < 4; hh++) sd[hh] = sdst[n * 4 + hh];

    float mloc[4] = {-1e30f, -1e30f, -1e30f, -1e30f};
    for (int e = e0 + tid; e < e1; e += 256) {
        int s = csr[e];
#pragma unroll
        for (int hh = 0; hh < 4; hh++) {
            float v = ssrc[s * 4 + hh] + sd[hh];
            v = v > 0.f ? v : 0.2f * v;
            mloc[hh] = fmaxf(mloc[hh], v);
        }
    }
    red[tid] = make_float4(mloc[0], mloc[1], mloc[2], mloc[3]);
    __syncthreads();
    for (int s = 128; s > 0; s >>= 1) {
        if (tid < s) {
            float4 a = red[tid], b = red[tid + s];
            a.x = fmaxf(a.x, b.x); a.y = fmaxf(a.y, b.y);
            a.z = fmaxf(a.z, b.z); a.w = fmaxf(a.w, b.w);
            red[tid] = a;
        }
        __syncthreads();
    }
    if (tid < 4) s_m[tid] = ((float*)&red[0])[tid];
    __syncthreads();
    float m0 = s_m[0], m1 = s_m[1], m2 = s_m[2], m3 = s_m[3];

    const int hh_ = tid >> 6;
    const int cb  = tid & 63;
    float acc0 = 0.f, acc1 = 0.f, acc2 = 0.f, acc3 = 0.f;
    float wsum[4] = {0.f, 0.f, 0.f, 0.f};

    for (int c0 = e0; c0 < e1; c0 += AGG_CHUNK) {
        int cnt = min(AGG_CHUNK, e1 - c0);
        for (int j = tid; j < cnt; j += 256) {
            int s = csr[c0 + j];
            s_src[j] = s;
            float v0 = ssrc[s * 4 + 0] + sd[0]; v0 = v0 > 0.f ? v0 : 0.2f * v0;
            float v1 = ssrc[s * 4 + 1] + sd[1]; v1 = v1 > 0.f ? v1 : 0.2f * v1;
            float v2 = ssrc[s * 4 + 2] + sd[2]; v2 = v2 > 0.f ? v2 : 0.2f * v2;
            float v3 = ssrc[s * 4 + 3] + sd[3]; v3 = v3 > 0.f ? v3 : 0.2f * v3;
            float w0 = __expf(v0 - m0), w1 = __expf(v1 - m1);
            float w2 = __expf(v2 - m2), w3 = __expf(v3 - m3);
            s_w[j * 4 + 0] = w0; s_w[j * 4 + 1] = w1;
            s_w[j * 4 + 2] = w2; s_w[j * 4 + 3] = w3;
            wsum[0] += w0; wsum[1] += w1; wsum[2] += w2; wsum[3] += w3;
        }
        __syncthreads();
        for (int j = 0; j < cnt; j++) {
            int s = s_src[j];
            float w = s_w[j * 4 + hh_];
            const float* hr = h + (size_t)s * HD + hh_ * DD + cb;
            acc0 += w * hr[0];
            acc1 += w * hr[64];
            acc2 += w * hr[128];
            acc3 += w * hr[192];
        }
        __syncthreads();
    }

    red[tid] = make_float4(wsum[0], wsum[1], wsum[2], wsum[3]);
    __syncthreads();
    for (int s = 128; s > 0; s >>= 1) {
        if (tid < s) {
            float4 a = red[tid], b = red[tid + s];
            a.x += b.x; a.y += b.y; a.z += b.z; a.w += b.w;
            red[tid] = a;
        }
        __syncthreads();
    }
    if (tid < 4) s_s[tid] = ((float*)&red[0])[tid];

    s_out[hh_ * 256 + cb]       = acc0;
    s_out[hh_ * 256 + cb + 64]  = acc1;
    s_out[hh_ * 256 + cb + 128] = acc2;
    s_out[hh_ * 256 + cb + 192] = acc3;
    __syncthreads();

    {
        int c = tid;
        float r = 0.f;
#pragma unroll
        for (int hh = 0; hh < 4; hh++)
            r += s_out[hh * 256 + c] / (s_s[hh] + 1e-16f);
        out[(size_t)n * DD + c] = f2tf_f(0.25f * r + bias[c]);
    }
}

// ---------------- fused concat + final FC ([768] -> 32) --------------------
__global__ void k_final(const float* __restrict__ d, const float* __restrict__ ai,
                        const float* __restrict__ ae, const float* __restrict__ W,
                        const float* __restrict__ b, float* __restrict__ out, int M)
{
    __shared__ float s_in[8][768];
    int r0 = blockIdx.x * 8;
    int tid = threadIdx.x;   // 256
    for (int idx = tid; idx < 8 * 768; idx += 256) {
        int rr = idx / 768, cc = idx - rr * 768;
        int r = r0 + rr;
        float v = 0.f;
        if (r < M) {
            if (cc < 256)      v = d [(size_t)r * 256 + cc];
            else if (cc < 512) v = ai[(size_t)r * 256 + cc - 256];
            else               v = ae[(size_t)r * 256 + cc - 512];
        }
        s_in[rr][cc] = v;
    }
    __syncthreads();
    int rr = tid >> 5, j = tid & 31;
    int r = r0 + rr;
    if (r < M) {
        float acc = b[j];
#pragma unroll 8
        for (int k = 0; k < 768; k++) acc += s_in[rr][k] * W[k * 32 + j];
        out[(size_t)r * 32 + j] = acc;
    }
}

// ---------------- host orchestration ---------------------------------------
enum { GM_PLAIN = 0, GM_BIASRELU = 1, GM_EXPSUM = 2, GM_NORM = 3 };

static inline void launch_gemm(const float* A, const float* B, float* C,
                               const float* aux, float* rowsum,
                               int M, int N, int K, bool transb, int mode)
{
    dim3 grid(N / 128, (M + 127) / 128);
    if (transb) {
        tgemm<true, GM_EXPSUM><<<grid, 256>>>(A, B, C, aux, rowsum, M, N, K);
    } else if (mode == GM_BIASRELU) {
        tgemm<false, GM_BIASRELU><<<grid, 256>>>(A, B, C, aux, rowsum, M, N, K);
    } else if (mode == GM_NORM) {
        tgemm<false, GM_NORM><<<grid, 256>>>(A, B, C, aux, rowsum, M, N, K);
    } else {
        tgemm<false, GM_PLAIN><<<grid, 256>>>(A, B, C, aux, rowsum, M, N, K);
    }
}

struct Ptrs {
    float *hd, *hi, *he, *ie, *ee, *ssrc, *sdst, *ssum, *gat, *dd, *ii, *ev, *S, *atti, *atte, *wtmp;
    int *deg, *off, *cur, *csr;
};

// x must already be tf32-rounded; W raw -> converted via wtmp inside.
static void run_gat(const float* x_tf, const float* W_raw, const float* a_src,
                    const float* a_dst, const float* bias,
                    const int* esrc, const int* edst,
                    int N, int E, int Din, float* hbuf, float* gat_out, const Ptrs& p)
{
    k_pretf<<<1024, 256>>>(W_raw, p.wtmp, Din * HD);
    launch_gemm(x_tf, p.wtmp, hbuf, nullptr, nullptr, N, HD, Din, false, GM_PLAIN);
    k_scores<<<N, 128>>>(hbuf, a_src, a_dst, p.ssrc, p.sdst, N);
    k_set_deg1<<<(N + 255) / 256, 256>>>(p.deg, N);
    k_count<<<(E + 255) / 256 > 2048 ? 2048 : (E + 255) / 256, 256>>>(edst, p.deg, E);
    k_exscan<<<1, 1024>>>(p.deg, p.off, p.cur, N);
    k_fill<<<(E + 255) / 256 > 2048 ? 2048 : (E + 255) / 256, 256>>>(esrc, edst, p.cur, p.csr, E);
    k_fill_self<<<(N + 255) / 256, 256>>>(p.cur, p.csr, N);
    k_gat_agg<<<N, 256>>>(hbuf, p.ssrc, p.sdst, p.off, p.csr, bias, gat_out, N);
}

extern "C" void kernel_launch(void* const* d_in, const int* in_sizes, int n_in,
                              void* d_out, int out_size)
{
    const float* x_d     = (const float*)d_in[0];
    const int*   idx_i   = (const int*)  d_in[1];
    const int*   idx_e   = (const int*)  d_in[2];
    const int*   eidx_d  = (const int*)  d_in[3];
    const int*   eidx_i  = (const int*)  d_in[4];
    const int*   eidx_e  = (const int*)  d_in[5];
    const float* emb_i   = (const float*)d_in[6];
    const float* emb_e   = (const float*)d_in[7];
    const float* Wd      = (const float*)d_in[8];
    const float* a_src_d = (const float*)d_in[9];
    const float* a_dst_d = (const float*)d_in[10];
    const float* bd      = (const float*)d_in[11];
    const float* Wi      = (const float*)d_in[12];
    const float* a_src_i = (const float*)d_in[13];
    const float* a_dst_i = (const float*)d_in[14];
    const float* bi      = (const float*)d_in[15];
    const float* We      = (const float*)d_in[16];
    const float* a_src_e = (const float*)d_in[17];
    const float* a_dst_e = (const float*)d_in[18];
    const float* be      = (const float*)d_in[19];
    const float* W_dfc   = (const float*)d_in[20];
    const float* b_dfc   = (const float*)d_in[21];
    const float* W_ifc   = (const float*)d_in[22];
    const float* b_ifc   = (const float*)d_in[23];
    const float* W_efc   = (const float*)d_in[24];
    const float* b_efc   = (const float*)d_in[25];
    const float* W_fc    = (const float*)d_in[26];
    const float* b_fc    = (const float*)d_in[27];
    float* out = (float*)d_out;

    const int Din = 512;
    const int Nd = in_sizes[0] / Din;
    const int Ni = in_sizes[1];
    const int Ne = in_sizes[2];
    const int Ed = in_sizes[3] / 2;
    const int Ei = in_sizes[4] / 2;
    const int Ee = in_sizes[5] / 2;

    Ptrs p;
    cudaGetSymbolAddress((void**)&p.hd,   g_hd);
    cudaGetSymbolAddress((void**)&p.hi,   g_hi);
    cudaGetSymbolAddress((void**)&p.he,   g_he);
    cudaGetSymbolAddress((void**)&p.ie,   g_ie);
    cudaGetSymbolAddress((void**)&p.ee,   g_ee);
    cudaGetSymbolAddress((void**)&p.ssrc, g_ssrc);
    cudaGetSymbolAddress((void**)&p.sdst, g_sdst);
    cudaGetSymbolAddress((void**)&p.ssum, g_ssum);
    cudaGetSymbolAddress((void**)&p.gat,  g_gat);
    cudaGetSymbolAddress((void**)&p.dd,   g_dd);
    cudaGetSymbolAddress((void**)&p.ii,   g_ii);
    cudaGetSymbolAddress((void**)&p.ev,   g_ev);
    cudaGetSymbolAddress((void**)&p.S,    g_S);
    cudaGetSymbolAddress((void**)&p.atti, g_atti);
    cudaGetSymbolAddress((void**)&p.atte, g_atte);
    cudaGetSymbolAddress((void**)&p.wtmp, g_wtmp);
    cudaGetSymbolAddress((void**)&p.deg,  g_deg);
    cudaGetSymbolAddress((void**)&p.off,  g_off);
    cudaGetSymbolAddress((void**)&p.cur,  g_cur);
    cudaGetSymbolAddress((void**)&p.csr,  g_csr);

    // embedding lookups (tf32-rounded on the fly)
    k_gather_emb<<<2048, 256>>>(emb_i, idx_i, p.ie, Ni);
    k_gather_emb<<<2048, 256>>>(emb_e, idx_e, p.ee, Ne);

    // x_d tf32 conversion into g_S scratch (g_S unused until attention phase)
    float* x_tf = p.S;
    k_pretf<<<4096, 256>>>(x_d, x_tf, Nd * Din);

    // dialogue branch: GAT + relu FC
    run_gat(x_tf, Wd, a_src_d, a_dst_d, bd, eidx_d, eidx_d + Ed, Nd, Ed, Din, p.hd, p.gat, p);
    k_pretf<<<256, 256>>>(W_dfc, p.wtmp, DD * DD);
    launch_gemm(p.gat, p.wtmp, p.dd, b_dfc, nullptr, Nd, DD, DD, false, GM_BIASRELU);

    // intention branch
    run_gat(p.ie, Wi, a_src_i, a_dst_i, bi, eidx_i, eidx_i + Ei, Ni, Ei, DD, p.hi, p.gat, p);
    k_pretf<<<256, 256>>>(W_ifc, p.wtmp, DD * DD);
    launch_gemm(p.gat, p.wtmp, p.ii, b_ifc, nullptr, Ni, DD, DD, false, GM_BIASRELU);

    // emotion branch
    run_gat(p.ee, We, a_src_e, a_dst_e, be, eidx_e, eidx_e + Ee, Ne, Ee, DD, p.he, p.gat, p);
    k_pretf<<<256, 256>>>(W_efc, p.wtmp, DD * DD);
    launch_gemm(p.gat, p.wtmp, p.ev, b_efc, nullptr, Ne, DD, DD, false, GM_BIASRELU);

    // cross attention: att_i = softmax(d @ i^T) @ i   (softmax fused into GEMMs)
    k_zero<<<(Nd + 255) / 256, 256>>>(p.ssum, Nd);
    launch_gemm(p.dd, p.ii, p.S, nullptr, p.ssum, Nd, Ni, DD, true, GM_EXPSUM);
    launch_gemm(p.S, p.ii, p.atti, p.ssum, nullptr, Nd, DD, Ni, false, GM_NORM);

    // att_e = softmax(d @ e^T) @ e
    k_zero<<<(Nd + 255) / 256, 256>>>(p.ssum, Nd);
    launch_gemm(p.dd, p.ev, p.S, nullptr, p.ssum, Nd, Ne, DD, true, GM_EXPSUM);
    launch_gemm(p.S, p.ev, p.atte, p.ssum, nullptr, Nd, DD, Ne, false, GM_NORM);

    // fused concat + final FC
    k_final<<<(Nd + 7) / 8, 256>>>(p.dd, p.atti, p.atte, W_fc, b_fc, out, Nd);
}

// round 10
// speedup vs baseline: 1.3722x; 1.0405x over previous
#include <cuda_runtime.h>
#include <math.h>
#include <stdint.h>

#define HEADS 4
#define DD 256
#define HD 1024            // HEADS * DD

#define MAXND 20000
#define MAXNI 4096
#define MAXED 640000
#define MAXET (MAXED + MAXND)

// ---------------- scratch (device globals; no allocation allowed) ----------
__device__ float g_hd  [(size_t)MAXND * HD];
__device__ float g_hi  [(size_t)MAXNI * HD];
__device__ float g_he  [(size_t)MAXNI * HD];
__device__ float g_ie  [(size_t)MAXNI * DD];
__device__ float g_ee  [(size_t)MAXNI * DD];
__device__ float g_ssrc[(size_t)MAXND * HEADS];
__device__ float g_sdst[(size_t)MAXND * HEADS];
__device__ float g_ssum[MAXND];                  // attention row sums
__device__ int   g_deg [MAXND];
__device__ int   g_off [MAXND + 1];
__device__ int   g_cur [MAXND];
__device__ int   g_csr [MAXET];
__device__ float g_gat [(size_t)MAXND * DD];
__device__ float g_dd  [(size_t)MAXND * DD];
__device__ float g_ii  [(size_t)MAXNI * DD];
__device__ float g_ev  [(size_t)MAXNI * DD];
__device__ float g_S   [(size_t)MAXND * 4096];   // also reused as x_d tf32 scratch
__device__ float g_atti[(size_t)MAXND * DD];
__device__ float g_atte[(size_t)MAXND * DD];
__device__ float g_wtmp[512 * 1024];             // converted weight scratch

// ---------------- helpers ---------------------------------------------------
__device__ __forceinline__ uint32_t f2tf(float f) {
    uint32_t u;
    asm("cvt.rna.tf32.f32 %0, %1;" : "=r"(u) : "f"(f));
    return u;
}
__device__ __forceinline__ float f2tf_f(float f) {
    return __uint_as_float(f2tf(f));
}
__device__ __forceinline__ uint32_t smem_u32(const void* p) {
    uint32_t a;
    asm("{ .reg .u64 t; cvta.to.shared.u64 t, %1; cvt.u32.u64 %0, t; }"
        : "=r"(a) : "l"(p));
    return a;
}
#define CPASYNC16(d, s, sz) \
    asm volatile("cp.async.cg.shared.global [%0], [%1], 16, %2;" \
                 :: "r"(d), "l"(s), "r"(sz))
#define CPCOMMIT() asm volatile("cp.async.commit_group;")

// ---------------- tf32 tensor-core GEMM, cp.async 3-stage pipeline ----------
// All operands MUST already hold tf32-rounded bit patterns (no cvt in loop).
// C[M,N] = A[M,K] @ B  (B: [K,N] row-major; [N,K] row-major if TRANSB)
// BM=BN=128, BK=16, 256 threads = 8 warps (4x2), warp tile 32x64 (m16n8k8).
// MODE: 0 plain, 1 bias+relu (tf32 out), 2 exp+rowsum (tf32 out), 3 /rowsum.
// 3 stages x (A 2560 + B 2560 floats) = 61440 B dynamic smem; ONE sync/iter.
#define TG_SMEM 61440
template<bool TRANSB, int MODE>
__global__ __launch_bounds__(256)
void tgemm(const float* __restrict__ A, const float* __restrict__ B,
           float* __restrict__ C, const float* __restrict__ aux,
           float* __restrict__ rowsum, int M, int N, int K)
{
    extern __shared__ float smp[];

    const int tid  = threadIdx.x;
    const int warp = tid >> 5, lane = tid & 31;
    const int g    = lane >> 2, tig = lane & 3;
    const int wm   = (warp >> 1) * 32;
    const int wn   = (warp & 1) * 64;
    const int row0 = blockIdx.y * 128, col0 = blockIdx.x * 128;

    float c[2][8][4];
#pragma unroll
    for (int i = 0; i < 2; i++)
#pragma unroll
        for (int j = 0; j < 8; j++)
#pragma unroll
            for (int q = 0; q < 4; q++) c[i][j][q] = 0.f;

    // stage s: A at smp + s*5120, B at smp + s*5120 + 2560
    uint32_t base_u32 = smem_u32(smp);

    const int nIter = K >> 4;

    auto load_stage = [&](int s, int k0) {
        uint32_t asb = base_u32 + s * 5120 * 4;
        uint32_t bsb = asb + 2560 * 4;
#pragma unroll
        for (int i = 0; i < 2; i++) {        // A: 128 rows x 16 k = 512 chunks
            int f = tid + 256 * i;
            int row = f >> 2, c4 = (f & 3) * 4;
            int gr = row0 + row;
            const float* src = A + (size_t)(gr < M ? gr : M - 1) * K + k0 + c4;
            CPASYNC16(asb + (row * 20 + c4) * 4, src, (gr < M) ? 16 : 0);
        }
#pragma unroll
        for (int i = 0; i < 2; i++) {        // B: 512 chunks
            int f = tid + 256 * i;
            if (TRANSB) {
                int n = f >> 2, k4 = (f & 3) * 4;
                const float* src = B + (size_t)(col0 + n) * K + k0 + k4;
                CPASYNC16(bsb + (n * 20 + k4) * 4, src, 16);
            } else {
                int k = f >> 5, n4 = (f & 31) * 4;
                const float* src = B + (size_t)(k0 + k) * N + col0 + n4;
                CPASYNC16(bsb + (k * 136 + n4) * 4, src, 16);
            }
        }
        CPCOMMIT();
    };

    // prologue: fill stages 0 and 1
    load_stage(0, 0);
    if (nIter > 1) load_stage(1, 16);

    int cur = 0, nxt2 = 2;   // nxt2 = (it+2) % 3
    for (int it = 0; it < nIter; it++) {
        if (it + 1 < nIter) {
            asm volatile("cp.async.wait_group 1;");
        } else {
            asm volatile("cp.async.wait_group 0;");
        }
        __syncthreads();

        if (it + 2 < nIter) load_stage(nxt2, (it + 2) << 4);

        const float* as_ = smp + cur * 5120;
        const float* bs_ = as_ + 2560;

#pragma unroll
        for (int ks = 0; ks < 2; ks++) {
            const int kk = ks * 8;
            uint32_t af[2][4], bf[8][2];
#pragma unroll
            for (int i = 0; i < 2; i++) {
                int m = wm + i * 16 + g;
                af[i][0] = __float_as_uint(as_[(size_t)m * 20 + kk + tig]);
                af[i][1] = __float_as_uint(as_[(size_t)(m + 8) * 20 + kk + tig]);
                af[i][2] = __float_as_uint(as_[(size_t)m * 20 + kk + tig + 4]);
                af[i][3] = __float_as_uint(as_[(size_t)(m + 8) * 20 + kk + tig + 4]);
            }
#pragma unroll
            for (int j = 0; j < 8; j++) {
                int n = wn + j * 8 + g;
                if (TRANSB) {
                    bf[j][0] = __float_as_uint(bs_[(size_t)n * 20 + kk + tig]);
                    bf[j][1] = __float_as_uint(bs_[(size_t)n * 20 + kk + tig + 4]);
                } else {
                    bf[j][0] = __float_as_uint(bs_[(size_t)(kk + tig) * 136 + n]);
                    bf[j][1] = __float_as_uint(bs_[(size_t)(kk + tig + 4) * 136 + n]);
                }
            }
#pragma unroll
            for (int i = 0; i < 2; i++)
#pragma unroll
                for (int j = 0; j < 8; j++) {
                    asm volatile(
                        "mma.sync.aligned.m16n8k8.row.col.f32.tf32.tf32.f32 "
                        "{%0,%1,%2,%3}, {%4,%5,%6,%7}, {%8,%9}, {%0,%1,%2,%3};"
                        : "+f"(c[i][j][0]), "+f"(c[i][j][1]),
                          "+f"(c[i][j][2]), "+f"(c[i][j][3])
                        : "r"(af[i][0]), "r"(af[i][1]), "r"(af[i][2]), "r"(af[i][3]),
                          "r"(bf[j][0]), "r"(bf[j][1]));
                }
        }

        cur = (cur + 1 == 3) ? 0 : cur + 1;
        nxt2 = (nxt2 + 1 == 3) ? 0 : nxt2 + 1;
    }

    // ---- epilogue ----
#pragma unroll
    for (int i = 0; i < 2; i++) {
        int r0 = row0 + wm + i * 16 + g;
        int r1 = r0 + 8;
        float inv0 = 1.f, inv1 = 1.f;
        if (MODE == 3) {
            if (r0 < M) inv0 = 1.f / (aux[r0] + 1e-16f);
            if (r1 < M) inv1 = 1.f / (aux[r1] + 1e-16f);
        }
        float p0 = 0.f, p1 = 0.f;
#pragma unroll
        for (int j = 0; j < 8; j++) {
            int cc = col0 + wn + j * 8 + tig * 2;
            float v0 = c[i][j][0], v1 = c[i][j][1];
            float v2 = c[i][j][2], v3 = c[i][j][3];
            if (MODE == 1) {
                float bb0 = aux[cc], bb1 = aux[cc + 1];
                v0 = f2tf_f(fmaxf(v0 + bb0, 0.f)); v1 = f2tf_f(fmaxf(v1 + bb1, 0.f));
                v2 = f2tf_f(fmaxf(v2 + bb0, 0.f)); v3 = f2tf_f(fmaxf(v3 + bb1, 0.f));
            }
            if (MODE == 2) {
                v0 = f2tf_f(__expf(v0)); v1 = f2tf_f(__expf(v1));
                v2 = f2tf_f(__expf(v2)); v3 = f2tf_f(__expf(v3));
                p0 += v0 + v1; p1 += v2 + v3;
            }
            if (MODE == 3) {
                v0 *= inv0; v1 *= inv0; v2 *= inv1; v3 *= inv1;
            }
            if (r0 < M) *(float2*)(C + (size_t)r0 * N + cc) = make_float2(v0, v1);
            if (r1 < M) *(float2*)(C + (size_t)r1 * N + cc) = make_float2(v2, v3);
        }
        if (MODE == 2) {
            // quad reduce: lanes 4g..4g+3 hold partials of rows r0/r1
            p0 += __shfl_down_sync(0xffffffffu, p0, 1);
            p0 += __shfl_down_sync(0xffffffffu, p0, 2);
            p1 += __shfl_down_sync(0xffffffffu, p1, 1);
            p1 += __shfl_down_sync(0xffffffffu, p1, 2);
            if (tig == 0) {
                if (r0 < M) atomicAdd(&rowsum[r0], p0);
                if (r1 < M) atomicAdd(&rowsum[r1], p1);
            }
        }
    }
}

// ---------------- misc small kernels ---------------------------------------
__global__ void k_zero(float* __restrict__ p, int n)
{
    int i = blockIdx.x * blockDim.x + threadIdx.x;
    if (i < n) p[i] = 0.f;
}

// elementwise tf32 rounding pass (for raw inputs used as GEMM operands)
__global__ void k_pretf(const float* __restrict__ in, float* __restrict__ out, int n)
{
    int i = blockIdx.x * blockDim.x + threadIdx.x;
    for (; i < n; i += gridDim.x * blockDim.x) out[i] = f2tf_f(in[i]);
}

__global__ void k_gather_emb(const float* __restrict__ table, const int* __restrict__ idx,
                             float* __restrict__ out, int N)
{
    int i = blockIdx.x * blockDim.x + threadIdx.x;
    int total = N * DD;
    for (; i < total; i += gridDim.x * blockDim.x) {
        int n = i / DD, c = i - n * DD;
        out[i] = f2tf_f(table[(size_t)idx[n] * DD + c]);
    }
}

__global__ void k_scores(const float* __restrict__ h, const float* __restrict__ a_src,
                         const float* __restrict__ a_dst,
                         float* __restrict__ ssrc, float* __restrict__ sdst, int N)
{
    int n = blockIdx.x;
    int tid = threadIdx.x;        // 128
    int hh = tid >> 5, lane = tid & 31;
    const float* hr = h + (size_t)n * HD + hh * DD;
    float s1 = 0.f, s2 = 0.f;
    for (int c = lane; c < DD; c += 32) {
        float v = hr[c];
        s1 += v * a_src[hh * DD + c];
        s2 += v * a_dst[hh * DD + c];
    }
#pragma unroll
    for (int o = 16; o > 0; o >>= 1) {
        s1 += __shfl_down_sync(0xffffffffu, s1, o);
        s2 += __shfl_down_sync(0xffffffffu, s2, o);
    }
    if (lane == 0) { ssrc[n * HEADS + hh] = s1; sdst[n * HEADS + hh] = s2; }
}

__global__ void k_set_deg1(int* deg, int N)
{
    int i = blockIdx.x * blockDim.x + threadIdx.x;
    if (i < N) deg[i] = 1;
}
__global__ void k_count(const int* __restrict__ dst, int* __restrict__ deg, int E)
{
    int i = blockIdx.x * blockDim.x + threadIdx.x;
    for (; i < E; i += gridDim.x * blockDim.x) atomicAdd(&deg[dst[i]], 1);
}

// warp-shuffle based exclusive scan, 1024 threads, chunked
__global__ void k_exscan(const int* __restrict__ deg, int* __restrict__ off,
                         int* __restrict__ cur, int N)
{
    __shared__ int wsum[32];
    __shared__ int carry_s;
    int tid = threadIdx.x, lane = tid & 31, w = tid >> 5;
    if (tid == 0) carry_s = 0;
    __syncthreads();
    for (int base = 0; base < N; base += 1024) {
        int i = base + tid;
        int v = (i < N) ? deg[i] : 0;
        int x = v;
#pragma unroll
        for (int o = 1; o < 32; o <<= 1) {
            int t = __shfl_up_sync(0xffffffffu, x, o);
            if (lane >= o) x += t;
        }
        if (lane == 31) wsum[w] = x;
        __syncthreads();
        if (w == 0) {
            int s = wsum[lane];
#pragma unroll
            for (int o = 1; o < 32; o <<= 1) {
                int t = __shfl_up_sync(0xffffffffu, s, o);
                if (lane >= o) s += t;
            }
            wsum[lane] = s;
        }
        __syncthreads();
        int excl = carry_s + (w > 0 ? wsum[w - 1] : 0) + x - v;
        if (i < N) { off[i] = excl; cur[i] = excl; }
        __syncthreads();
        if (tid == 0) carry_s += wsum[31];
        __syncthreads();
    }
    if (tid == 0) off[N] = carry_s;
}
__global__ void k_fill(const int* __restrict__ src, const int* __restrict__ dst,
                       int* __restrict__ cur, int* __restrict__ csr, int E)
{
    int i = blockIdx.x * blockDim.x + threadIdx.x;
    for (; i < E; i += gridDim.x * blockDim.x) {
        int p = atomicAdd(&cur[dst[i]], 1);
        csr[p] = src[i];
    }
}
__global__ void k_fill_self(int* __restrict__ cur, int* __restrict__ csr, int N)
{
    int i = blockIdx.x * blockDim.x + threadIdx.x;
    if (i < N) { int p = atomicAdd(&cur[i], 1); csr[p] = i; }
}

// ---------------- GAT aggregation: one block per destination node ----------
#define AGG_CHUNK 512
__global__ void k_gat_agg(const float* __restrict__ h,      // [N, HD]
                          const float* __restrict__ ssrc,   // [N, 4]
                          const float* __restrict__ sdst,   // [N, 4]
                          const int* __restrict__ off, const int* __restrict__ csr,
                          const float* __restrict__ bias,   // [256]
                          float* __restrict__ out, int N)   // [N, 256] (tf32-rounded)
{
    const int n = blockIdx.x;
    const int tid = threadIdx.x;      // 256
    const int e0 = off[n], e1 = off[n + 1];

    __shared__ int    s_src[AGG_CHUNK];
    __shared__ float  s_w[AGG_CHUNK * 4];
    __shared__ float4 red[256];
    __shared__ float  s_m[4], s_s[4];
    __shared__ float  s_out[1024];

    float sd[4];
#pragma unroll
    for (int hh = 0; hh < 4; hh++) sd[hh] = sdst[n * 4 + hh];

    float mloc[4] = {-1e30f, -1e30f, -1e30f, -1e30f};
    for (int e = e0 + tid; e < e1; e += 256) {
        int s = csr[e];
#pragma unroll
        for (int hh = 0; hh < 4; hh++) {
            float v = ssrc[s * 4 + hh] + sd[hh];
            v = v > 0.f ? v : 0.2f * v;
            mloc[hh] = fmaxf(mloc[hh], v);
        }
    }
    red[tid] = make_float4(mloc[0], mloc[1], mloc[2], mloc[3]);
    __syncthreads();
    for (int s = 128; s > 0; s >>= 1) {
        if (tid < s) {
            float4 a = red[tid], b = red[tid + s];
            a.x = fmaxf(a.x, b.x); a.y = fmaxf(a.y, b.y);
            a.z = fmaxf(a.z, b.z); a.w = fmaxf(a.w, b.w);
            red[tid] = a;
        }
        __syncthreads();
    }
    if (tid < 4) s_m[tid] = ((float*)&red[0])[tid];
    __syncthreads();
    float m0 = s_m[0], m1 = s_m[1], m2 = s_m[2], m3 = s_m[3];

    const int hh_ = tid >> 6;
    const int cb  = tid & 63;
    float acc0 = 0.f, acc1 = 0.f, acc2 = 0.f, acc3 = 0.f;
    float wsum[4] = {0.f, 0.f, 0.f, 0.f};

    for (int c0 = e0; c0 < e1; c0 += AGG_CHUNK) {
        int cnt = min(AGG_CHUNK, e1 - c0);
        for (int j = tid; j < cnt; j += 256) {
            int s = csr[c0 + j];
            s_src[j] = s;
            float v0 = ssrc[s * 4 + 0] + sd[0]; v0 = v0 > 0.f ? v0 : 0.2f * v0;
            float v1 = ssrc[s * 4 + 1] + sd[1]; v1 = v1 > 0.f ? v1 : 0.2f * v1;
            float v2 = ssrc[s * 4 + 2] + sd[2]; v2 = v2 > 0.f ? v2 : 0.2f * v2;
            float v3 = ssrc[s * 4 + 3] + sd[3]; v3 = v3 > 0.f ? v3 : 0.2f * v3;
            float w0 = __expf(v0 - m0), w1 = __expf(v1 - m1);
            float w2 = __expf(v2 - m2), w3 = __expf(v3 - m3);
            s_w[j * 4 + 0] = w0; s_w[j * 4 + 1] = w1;
            s_w[j * 4 + 2] = w2; s_w[j * 4 + 3] = w3;
            wsum[0] += w0; wsum[1] += w1; wsum[2] += w2; wsum[3] += w3;
        }
        __syncthreads();
        for (int j = 0; j < cnt; j++) {
            int s = s_src[j];
            float w = s_w[j * 4 + hh_];
            const float* hr = h + (size_t)s * HD + hh_ * DD + cb;
            acc0 += w * hr[0];
            acc1 += w * hr[64];
            acc2 += w * hr[128];
            acc3 += w * hr[192];
        }
        __syncthreads();
    }

    red[tid] = make_float4(wsum[0], wsum[1], wsum[2], wsum[3]);
    __syncthreads();
    for (int s = 128; s > 0; s >>= 1) {
        if (tid < s) {
            float4 a = red[tid], b = red[tid + s];
            a.x += b.x; a.y += b.y; a.z += b.z; a.w += b.w;
            red[tid] = a;
        }
        __syncthreads();
    }
    if (tid < 4) s_s[tid] = ((float*)&red[0])[tid];

    s_out[hh_ * 256 + cb]       = acc0;
    s_out[hh_ * 256 + cb + 64]  = acc1;
    s_out[hh_ * 256 + cb + 128] = acc2;
    s_out[hh_ * 256 + cb + 192] = acc3;
    __syncthreads();

    {
        int c = tid;
        float r = 0.f;
#pragma unroll
        for (int hh = 0; hh < 4; hh++)
            r += s_out[hh * 256 + c] / (s_s[hh] + 1e-16f);
        out[(size_t)n * DD + c] = f2tf_f(0.25f * r + bias[c]);
    }
}

// ---------------- fused concat + final FC ([768] -> 32) --------------------
__global__ void k_final(const float* __restrict__ d, const float* __restrict__ ai,
                        const float* __restrict__ ae, const float* __restrict__ W,
                        const float* __restrict__ b, float* __restrict__ out, int M)
{
    __shared__ float s_in[8][768];
    int r0 = blockIdx.x * 8;
    int tid = threadIdx.x;   // 256
    for (int idx = tid; idx < 8 * 768; idx += 256) {
        int rr = idx / 768, cc = idx - rr * 768;
        int r = r0 + rr;
        float v = 0.f;
        if (r < M) {
            if (cc < 256)      v = d [(size_t)r * 256 + cc];
            else if (cc < 512) v = ai[(size_t)r * 256 + cc - 256];
            else               v = ae[(size_t)r * 256 + cc - 512];
        }
        s_in[rr][cc] = v;
    }
    __syncthreads();
    int rr = tid >> 5, j = tid & 31;
    int r = r0 + rr;
    if (r < M) {
        float acc = b[j];
#pragma unroll 8
        for (int k = 0; k < 768; k++) acc += s_in[rr][k] * W[k * 32 + j];
        out[(size_t)r * 32 + j] = acc;
    }
}

// ---------------- host orchestration ---------------------------------------
enum { GM_PLAIN = 0, GM_BIASRELU = 1, GM_EXPSUM = 2, GM_NORM = 3 };

static bool g_attr_set = false;

static inline void launch_gemm(const float* A, const float* B, float* C,
                               const float* aux, float* rowsum,
                               int M, int N, int K, bool transb, int mode)
{
    if (!g_attr_set) {
        cudaFuncSetAttribute(tgemm<true,  GM_EXPSUM>,  cudaFuncAttributeMaxDynamicSharedMemorySize, TG_SMEM);
        cudaFuncSetAttribute(tgemm<false, GM_BIASRELU>, cudaFuncAttributeMaxDynamicSharedMemorySize, TG_SMEM);
        cudaFuncSetAttribute(tgemm<false, GM_NORM>,    cudaFuncAttributeMaxDynamicSharedMemorySize, TG_SMEM);
        cudaFuncSetAttribute(tgemm<false, GM_PLAIN>,   cudaFuncAttributeMaxDynamicSharedMemorySize, TG_SMEM);
        g_attr_set = true;
    }
    dim3 grid(N / 128, (M + 127) / 128);
    if (transb) {
        tgemm<true, GM_EXPSUM><<<grid, 256, TG_SMEM>>>(A, B, C, aux, rowsum, M, N, K);
    } else if (mode == GM_BIASRELU) {
        tgemm<false, GM_BIASRELU><<<grid, 256, TG_SMEM>>>(A, B, C, aux, rowsum, M, N, K);
    } else if (mode == GM_NORM) {
        tgemm<false, GM_NORM><<<grid, 256, TG_SMEM>>>(A, B, C, aux, rowsum, M, N, K);
    } else {
        tgemm<false, GM_PLAIN><<<grid, 256, TG_SMEM>>>(A, B, C, aux, rowsum, M, N, K);
    }
}

struct Ptrs {
    float *hd, *hi, *he, *ie, *ee, *ssrc, *sdst, *ssum, *gat, *dd, *ii, *ev, *S, *atti, *atte, *wtmp;
    int *deg, *off, *cur, *csr;
};

// x must already be tf32-rounded; W raw -> converted via wtmp inside.
static void run_gat(const float* x_tf, const float* W_raw, const float* a_src,
                    const float* a_dst, const float* bias,
                    const int* esrc, const int* edst,
                    int N, int E, int Din, float* hbuf, float* gat_out, const Ptrs& p)
{
    k_pretf<<<1024, 256>>>(W_raw, p.wtmp, Din * HD);
    launch_gemm(x_tf, p.wtmp, hbuf, nullptr, nullptr, N, HD, Din, false, GM_PLAIN);
    k_scores<<<N, 128>>>(hbuf, a_src, a_dst, p.ssrc, p.sdst, N);
    k_set_deg1<<<(N + 255) / 256, 256>>>(p.deg, N);
    k_count<<<(E + 255) / 256 > 2048 ? 2048 : (E + 255) / 256, 256>>>(edst, p.deg, E);
    k_exscan<<<1, 1024>>>(p.deg, p.off, p.cur, N);
    k_fill<<<(E + 255) / 256 > 2048 ? 2048 : (E + 255) / 256, 256>>>(esrc, edst, p.cur, p.csr, E);
    k_fill_self<<<(N + 255) / 256, 256>>>(p.cur, p.csr, N);
    k_gat_agg<<<N, 256>>>(hbuf, p.ssrc, p.sdst, p.off, p.csr, bias, gat_out, N);
}

extern "C" void kernel_launch(void* const* d_in, const int* in_sizes, int n_in,
                              void* d_out, int out_size)
{
    const float* x_d     = (const float*)d_in[0];
    const int*   idx_i   = (const int*)  d_in[1];
    const int*   idx_e   = (const int*)  d_in[2];
    const int*   eidx_d  = (const int*)  d_in[3];
    const int*   eidx_i  = (const int*)  d_in[4];
    const int*   eidx_e  = (const int*)  d_in[5];
    const float* emb_i   = (const float*)d_in[6];
    const float* emb_e   = (const float*)d_in[7];
    const float* Wd      = (const float*)d_in[8];
    const float* a_src_d = (const float*)d_in[9];
    const float* a_dst_d = (const float*)d_in[10];
    const float* bd      = (const float*)d_in[11];
    const float* Wi      = (const float*)d_in[12];
    const float* a_src_i = (const float*)d_in[13];
    const float* a_dst_i = (const float*)d_in[14];
    const float* bi      = (const float*)d_in[15];
    const float* We      = (const float*)d_in[16];
    const float* a_src_e = (const float*)d_in[17];
    const float* a_dst_e = (const float*)d_in[18];
    const float* be      = (const float*)d_in[19];
    const float* W_dfc   = (const float*)d_in[20];
    const float* b_dfc   = (const float*)d_in[21];
    const float* W_ifc   = (const float*)d_in[22];
    const float* b_ifc   = (const float*)d_in[23];
    const float* W_efc   = (const float*)d_in[24];
    const float* b_efc   = (const float*)d_in[25];
    const float* W_fc    = (const float*)d_in[26];
    const float* b_fc    = (const float*)d_in[27];
    float* out = (float*)d_out;

    const int Din = 512;
    const int Nd = in_sizes[0] / Din;
    const int Ni = in_sizes[1];
    const int Ne = in_sizes[2];
    const int Ed = in_sizes[3] / 2;
    const int Ei = in_sizes[4] / 2;
    const int Ee = in_sizes[5] / 2;

    Ptrs p;
    cudaGetSymbolAddress((void**)&p.hd,   g_hd);
    cudaGetSymbolAddress((void**)&p.hi,   g_hi);
    cudaGetSymbolAddress((void**)&p.he,   g_he);
    cudaGetSymbolAddress((void**)&p.ie,   g_ie);
    cudaGetSymbolAddress((void**)&p.ee,   g_ee);
    cudaGetSymbolAddress((void**)&p.ssrc, g_ssrc);
    cudaGetSymbolAddress((void**)&p.sdst, g_sdst);
    cudaGetSymbolAddress((void**)&p.ssum, g_ssum);
    cudaGetSymbolAddress((void**)&p.gat,  g_gat);
    cudaGetSymbolAddress((void**)&p.dd,   g_dd);
    cudaGetSymbolAddress((void**)&p.ii,   g_ii);
    cudaGetSymbolAddress((void**)&p.ev,   g_ev);
    cudaGetSymbolAddress((void**)&p.S,    g_S);
    cudaGetSymbolAddress((void**)&p.atti, g_atti);
    cudaGetSymbolAddress((void**)&p.atte, g_atte);
    cudaGetSymbolAddress((void**)&p.wtmp, g_wtmp);
    cudaGetSymbolAddress((void**)&p.deg,  g_deg);
    cudaGetSymbolAddress((void**)&p.off,  g_off);
    cudaGetSymbolAddress((void**)&p.cur,  g_cur);
    cudaGetSymbolAddress((void**)&p.csr,  g_csr);

    // embedding lookups (tf32-rounded on the fly)
    k_gather_emb<<<2048, 256>>>(emb_i, idx_i, p.ie, Ni);
    k_gather_emb<<<2048, 256>>>(emb_e, idx_e, p.ee, Ne);

    // x_d tf32 conversion into g_S scratch (g_S unused until attention phase)
    float* x_tf = p.S;
    k_pretf<<<4096, 256>>>(x_d, x_tf, Nd * Din);

    // dialogue branch: GAT + relu FC
    run_gat(x_tf, Wd, a_src_d, a_dst_d, bd, eidx_d, eidx_d + Ed, Nd, Ed, Din, p.hd, p.gat, p);
    k_pretf<<<256, 256>>>(W_dfc, p.wtmp, DD * DD);
    launch_gemm(p.gat, p.wtmp, p.dd, b_dfc, nullptr, Nd, DD, DD, false, GM_BIASRELU);

    // intention branch
    run_gat(p.ie, Wi, a_src_i, a_dst_i, bi, eidx_i, eidx_i + Ei, Ni, Ei, DD, p.hi, p.gat, p);
    k_pretf<<<256, 256>>>(W_ifc, p.wtmp, DD * DD);
    launch_gemm(p.gat, p.wtmp, p.ii, b_ifc, nullptr, Ni, DD, DD, false, GM_BIASRELU);

    // emotion branch
    run_gat(p.ee, We, a_src_e, a_dst_e, be, eidx_e, eidx_e + Ee, Ne, Ee, DD, p.he, p.gat, p);
    k_pretf<<<256, 256>>>(W_efc, p.wtmp, DD * DD);
    launch_gemm(p.gat, p.wtmp, p.ev, b_efc, nullptr, Ne, DD, DD, false, GM_BIASRELU);

    // cross attention: att_i = softmax(d @ i^T) @ i   (softmax fused into GEMMs)
    k_zero<<<(Nd + 255) / 256, 256>>>(p.ssum, Nd);
    launch_gemm(p.dd, p.ii, p.S, nullptr, p.ssum, Nd, Ni, DD, true, GM_EXPSUM);
    launch_gemm(p.S, p.ii, p.atti, p.ssum, nullptr, Nd, DD, Ni, false, GM_NORM);

    // att_e = softmax(d @ e^T) @ e
    k_zero<<<(Nd + 255) / 256, 256>>>(p.ssum, Nd);
    launch_gemm(p.dd, p.ev, p.S, nullptr, p.ssum, Nd, Ne, DD, true, GM_EXPSUM);
    launch_gemm(p.S, p.ev, p.atte, p.ssum, nullptr, Nd, DD, Ne, false, GM_NORM);

    // fused concat + final FC
    k_final<<<(Nd + 7) / 8, 256>>>(p.dd, p.atti, p.atte, W_fc, b_fc, out, Nd);
}

// round 13
// speedup vs baseline: 1.5576x; 1.1351x over previous
#include <cuda_runtime.h>
#include <math.h>
#include <stdint.h>

#define HEADS 4
#define DD 256
#define HD 1024            // HEADS * DD

#define MAXND 20000
#define MAXNI 4096
#define MAXED 640000
#define MAXET (MAXED + MAXND)
#define MAXEI (MAXNI * 17)   // branch edges (64K) + self loops

// ---------------- scratch (device globals; no allocation allowed) ----------
__device__ float g_hd  [(size_t)MAXND * HD];
__device__ float g_hi  [(size_t)MAXNI * HD];
__device__ float g_he  [(size_t)MAXNI * HD];
__device__ float g_ie  [(size_t)MAXNI * DD];
__device__ float g_ee  [(size_t)MAXNI * DD];
__device__ float g_ssrc [(size_t)MAXND * HEADS];
__device__ float g_sdst [(size_t)MAXND * HEADS];
__device__ float g_ssrc2[(size_t)MAXNI * HEADS];
__device__ float g_sdst2[(size_t)MAXNI * HEADS];
__device__ float g_ssrc3[(size_t)MAXNI * HEADS];
__device__ float g_sdst3[(size_t)MAXNI * HEADS];
__device__ float g_ssum [MAXND];
__device__ float g_ssum2[MAXND];
__device__ int   g_deg [MAXND];
__device__ int   g_off [MAXND + 1];
__device__ int   g_cur [MAXND];
__device__ int   g_csr [MAXET];
__device__ int   g_deg2[MAXNI];
__device__ int   g_off2[MAXNI + 1];
__device__ int   g_cur2[MAXNI];
__device__ int   g_csr2[MAXEI];
__device__ int   g_deg3[MAXNI];
__device__ int   g_off3[MAXNI + 1];
__device__ int   g_cur3[MAXNI];
__device__ int   g_csr3[MAXEI];
__device__ float g_gat  [(size_t)MAXND * DD];
__device__ float g_gat2 [(size_t)MAXNI * DD];
__device__ float g_gat3 [(size_t)MAXNI * DD];
__device__ float g_dd  [(size_t)MAXND * DD];
__device__ float g_ii  [(size_t)MAXNI * DD];
__device__ float g_ev  [(size_t)MAXNI * DD];
__device__ float g_S   [(size_t)MAXND * 4096];   // chain-i scores; also x_d tf32 scratch
__device__ float g_S2  [(size_t)MAXND * 4096];   // chain-e scores
__device__ float g_atti[(size_t)MAXND * DD];
__device__ float g_atte[(size_t)MAXND * DD];
__device__ float g_wtmp [512 * 1024];            // dialogue weight scratch
__device__ float g_wtmp2[256 * 1024];            // intention weight scratch
__device__ float g_wtmp3[256 * 1024];            // emotion weight scratch

// ---------------- helpers ---------------------------------------------------
__device__ __forceinline__ uint32_t f2tf(float f) {
    uint32_t u;
    asm("cvt.rna.tf32.f32 %0, %1;" : "=r"(u) : "f"(f));
    return u;
}
__device__ __forceinline__ float f2tf_f(float f) {
    return __uint_as_float(f2tf(f));
}
__device__ __forceinline__ uint32_t smem_u32(const void* p) {
    uint32_t a;
    asm("{ .reg .u64 t; cvta.to.shared.u64 t, %1; cvt.u32.u64 %0, t; }"
        : "=r"(a) : "l"(p));
    return a;
}
#define CPASYNC16(d, s, sz) \
    asm volatile("cp.async.cg.shared.global [%0], [%1], 16, %2;" \
                 :: "r"(d), "l"(s), "r"(sz))
#define CPCOMMIT() asm volatile("cp.async.commit_group;")

// ---------------- tf32 tensor-core GEMM, cp.async 3-stage pipeline ----------
// All operands MUST already hold tf32-rounded bit patterns (no cvt in loop).
// C[M,N] = A[M,K] @ B  (B: [K,N] row-major; [N,K] row-major if TRANSB)
// BM=BN=128, BK=16, 256 threads = 8 warps (4x2), warp tile 32x64 (m16n8k8).
// MODE: 0 plain, 1 bias+relu (tf32 out), 2 exp+rowsum (tf32 out), 3 /rowsum.
// 3 stages x (A 2560 + B 2560 floats) = 61440 B dynamic smem; ONE sync/iter.
#define TG_SMEM 61440
template<bool TRANSB, int MODE>
__global__ __launch_bounds__(256)
void tgemm(const float* __restrict__ A, const float* __restrict__ B,
           float* __restrict__ C, const float* __restrict__ aux,
           float* __restrict__ rowsum, int M, int N, int K)
{
    extern __shared__ float smp[];

    const int tid  = threadIdx.x;
    const int warp = tid >> 5, lane = tid & 31;
    const int g    = lane >> 2, tig = lane & 3;
    const int wm   = (warp >> 1) * 32;
    const int wn   = (warp & 1) * 64;
    const int row0 = blockIdx.y * 128, col0 = blockIdx.x * 128;

    float c[2][8][4];
#pragma unroll
    for (int i = 0; i < 2; i++)
#pragma unroll
        for (int j = 0; j < 8; j++)
#pragma unroll
            for (int q = 0; q < 4; q++) c[i][j][q] = 0.f;

    uint32_t base_u32 = smem_u32(smp);
    const int nIter = K >> 4;

    auto load_stage = [&](int s, int k0) {
        uint32_t asb = base_u32 + s * 5120 * 4;
        uint32_t bsb = asb + 2560 * 4;
#pragma unroll
        for (int i = 0; i < 2; i++) {        // A: 128 rows x 16 k = 512 chunks
            int f = tid + 256 * i;
            int row = f >> 2, c4 = (f & 3) * 4;
            int gr = row0 + row;
            const float* src = A + (size_t)(gr < M ? gr : M - 1) * K + k0 + c4;
            CPASYNC16(asb + (row * 20 + c4) * 4, src, (gr < M) ? 16 : 0);
        }
#pragma unroll
        for (int i = 0; i < 2; i++) {        // B: 512 chunks
            int f = tid + 256 * i;
            if (TRANSB) {
                int n = f >> 2, k4 = (f & 3) * 4;
                const float* src = B + (size_t)(col0 + n) * K + k0 + k4;
                CPASYNC16(bsb + (n * 20 + k4) * 4, src, 16);
            } else {
                int k = f >> 5, n4 = (f & 31) * 4;
                const float* src = B + (size_t)(k0 + k) * N + col0 + n4;
                CPASYNC16(bsb + (k * 136 + n4) * 4, src, 16);
            }
        }
        CPCOMMIT();
    };

    load_stage(0, 0);
    if (nIter > 1) load_stage(1, 16);

    int cur = 0, nxt2 = 2;
    for (int it = 0; it < nIter; it++) {
        if (it + 1 < nIter) {
            asm volatile("cp.async.wait_group 1;");
        } else {
            asm volatile("cp.async.wait_group 0;");
        }
        __syncthreads();

        if (it + 2 < nIter) load_stage(nxt2, (it + 2) << 4);

        const float* as_ = smp + cur * 5120;
        const float* bs_ = as_ + 2560;

#pragma unroll
        for (int ks = 0; ks < 2; ks++) {
            const int kk = ks * 8;
            uint32_t af[2][4], bf[8][2];
#pragma unroll
            for (int i = 0; i < 2; i++) {
                int m = wm + i * 16 + g;
                af[i][0] = __float_as_uint(as_[(size_t)m * 20 + kk + tig]);
                af[i][1] = __float_as_uint(as_[(size_t)(m + 8) * 20 + kk + tig]);
                af[i][2] = __float_as_uint(as_[(size_t)m * 20 + kk + tig + 4]);
                af[i][3] = __float_as_uint(as_[(size_t)(m + 8) * 20 + kk + tig + 4]);
            }
#pragma unroll
            for (int j = 0; j < 8; j++) {
                int n = wn + j * 8 + g;
                if (TRANSB) {
                    bf[j][0] = __float_as_uint(bs_[(size_t)n * 20 + kk + tig]);
                    bf[j][1] = __float_as_uint(bs_[(size_t)n * 20 + kk + tig + 4]);
                } else {
                    bf[j][0] = __float_as_uint(bs_[(size_t)(kk + tig) * 136 + n]);
                    bf[j][1] = __float_as_uint(bs_[(size_t)(kk + tig + 4) * 136 + n]);
                }
            }
#pragma unroll
            for (int i = 0; i < 2; i++)
#pragma unroll
                for (int j = 0; j < 8; j++) {
                    asm volatile(
                        "mma.sync.aligned.m16n8k8.row.col.f32.tf32.tf32.f32 "
                        "{%0,%1,%2,%3}, {%4,%5,%6,%7}, {%8,%9}, {%0,%1,%2,%3};"
                        : "+f"(c[i][j][0]), "+f"(c[i][j][1]),
                          "+f"(c[i][j][2]), "+f"(c[i][j][3])
                        : "r"(af[i][0]), "r"(af[i][1]), "r"(af[i][2]), "r"(af[i][3]),
                          "r"(bf[j][0]), "r"(bf[j][1]));
                }
        }

        cur = (cur + 1 == 3) ? 0 : cur + 1;
        nxt2 = (nxt2 + 1 == 3) ? 0 : nxt2 + 1;
    }

    // ---- epilogue ----
#pragma unroll
    for (int i = 0; i < 2; i++) {
        int r0 = row0 + wm + i * 16 + g;
        int r1 = r0 + 8;
        float inv0 = 1.f, inv1 = 1.f;
        if (MODE == 3) {
            if (r0 < M) inv0 = 1.f / (aux[r0] + 1e-16f);
            if (r1 < M) inv1 = 1.f / (aux[r1] + 1e-16f);
        }
        float p0 = 0.f, p1 = 0.f;
#pragma unroll
        for (int j = 0; j < 8; j++) {
            int cc = col0 + wn + j * 8 + tig * 2;
            float v0 = c[i][j][0], v1 = c[i][j][1];
            float v2 = c[i][j][2], v3 = c[i][j][3];
            if (MODE == 1) {
                float bb0 = aux[cc], bb1 = aux[cc + 1];
                v0 = f2tf_f(fmaxf(v0 + bb0, 0.f)); v1 = f2tf_f(fmaxf(v1 + bb1, 0.f));
                v2 = f2tf_f(fmaxf(v2 + bb0, 0.f)); v3 = f2tf_f(fmaxf(v3 + bb1, 0.f));
            }
            if (MODE == 2) {
                v0 = f2tf_f(__expf(v0)); v1 = f2tf_f(__expf(v1));
                v2 = f2tf_f(__expf(v2)); v3 = f2tf_f(__expf(v3));
                p0 += v0 + v1; p1 += v2 + v3;
            }
            if (MODE == 3) {
                v0 *= inv0; v1 *= inv0; v2 *= inv1; v3 *= inv1;
            }
            if (r0 < M) *(float2*)(C + (size_t)r0 * N + cc) = make_float2(v0, v1);
            if (r1 < M) *(float2*)(C + (size_t)r1 * N + cc) = make_float2(v2, v3);
        }
        if (MODE == 2) {
            p0 += __shfl_down_sync(0xffffffffu, p0, 1);
            p0 += __shfl_down_sync(0xffffffffu, p0, 2);
            p1 += __shfl_down_sync(0xffffffffu, p1, 1);
            p1 += __shfl_down_sync(0xffffffffu, p1, 2);
            if (tig == 0) {
                if (r0 < M) atomicAdd(&rowsum[r0], p0);
                if (r1 < M) atomicAdd(&rowsum[r1], p1);
            }
        }
    }
}

// ---------------- misc small kernels ---------------------------------------
__global__ void k_zero(float* __restrict__ p, int n)
{
    int i = blockIdx.x * blockDim.x + threadIdx.x;
    if (i < n) p[i] = 0.f;
}

__global__ void k_pretf(const float* __restrict__ in, float* __restrict__ out, int n)
{
    int i = blockIdx.x * blockDim.x + threadIdx.x;
    for (; i < n; i += gridDim.x * blockDim.x) out[i] = f2tf_f(in[i]);
}

__global__ void k_gather_emb(const float* __restrict__ table, const int* __restrict__ idx,
                             float* __restrict__ out, int N)
{
    int i = blockIdx.x * blockDim.x + threadIdx.x;
    int total = N * DD;
    for (; i < total; i += gridDim.x * blockDim.x) {
        int n = i / DD, c = i - n * DD;
        out[i] = f2tf_f(table[(size_t)idx[n] * DD + c]);
    }
}

__global__ void k_scores(const float* __restrict__ h, const float* __restrict__ a_src,
                         const float* __restrict__ a_dst,
                         float* __restrict__ ssrc, float* __restrict__ sdst, int N)
{
    int n = blockIdx.x;
    int tid = threadIdx.x;        // 128
    int hh = tid >> 5, lane = tid & 31;
    const float* hr = h + (size_t)n * HD + hh * DD;
    float s1 = 0.f, s2 = 0.f;
    for (int c = lane; c < DD; c += 32) {
        float v = hr[c];
        s1 += v * a_src[hh * DD + c];
        s2 += v * a_dst[hh * DD + c];
    }
#pragma unroll
    for (int o = 16; o > 0; o >>= 1) {
        s1 += __shfl_down_sync(0xffffffffu, s1, o);
        s2 += __shfl_down_sync(0xffffffffu, s2, o);
    }
    if (lane == 0) { ssrc[n * HEADS + hh] = s1; sdst[n * HEADS + hh] = s2; }
}

__global__ void k_set_deg1(int* deg, int N)
{
    int i = blockIdx.x * blockDim.x + threadIdx.x;
    if (i < N) deg[i] = 1;
}
__global__ void k_count(const int* __restrict__ dst, int* __restrict__ deg, int E)
{
    int i = blockIdx.x * blockDim.x + threadIdx.x;
    for (; i < E; i += gridDim.x * blockDim.x) atomicAdd(&deg[dst[i]], 1);
}

__global__ void k_exscan(const int* __restrict__ deg, int* __restrict__ off,
                         int* __restrict__ cur, int N)
{
    __shared__ int wsum[32];
    __shared__ int carry_s;
    int tid = threadIdx.x, lane = tid & 31, w = tid >> 5;
    if (tid == 0) carry_s = 0;
    __syncthreads();
    for (int base = 0; base < N; base += 1024) {
        int i = base + tid;
        int v = (i < N) ? deg[i] : 0;
        int x = v;
#pragma unroll
        for (int o = 1; o < 32; o <<= 1) {
            int t = __shfl_up_sync(0xffffffffu, x, o);
            if (lane >= o) x += t;
        }
        if (lane == 31) wsum[w] = x;
        __syncthreads();
        if (w == 0) {
            int s = wsum[lane];
#pragma unroll
            for (int o = 1; o < 32; o <<= 1) {
                int t = __shfl_up_sync(0xffffffffu, s, o);
                if (lane >= o) s += t;
            }
            wsum[lane] = s;
        }
        __syncthreads();
        int excl = carry_s + (w > 0 ? wsum[w - 1] : 0) + x - v;
        if (i < N) { off[i] = excl; cur[i] = excl; }
        __syncthreads();
        if (tid == 0) carry_s += wsum[31];
        __syncthreads();
    }
    if (tid == 0) off[N] = carry_s;
}
__global__ void k_fill(const int* __restrict__ src, const int* __restrict__ dst,
                       int* __restrict__ cur, int* __restrict__ csr, int E)
{
    int i = blockIdx.x * blockDim.x + threadIdx.x;
    for (; i < E; i += gridDim.x * blockDim.x) {
        int p = atomicAdd(&cur[dst[i]], 1);
        csr[p] = src[i];
    }
}
__global__ void k_fill_self(int* __restrict__ cur, int* __restrict__ csr, int N)
{
    int i = blockIdx.x * blockDim.x + threadIdx.x;
    if (i < N) { int p = atomicAdd(&cur[i], 1); csr[p] = i; }
}

// ---------------- GAT aggregation: one block per destination node ----------
#define AGG_CHUNK 512
__global__ void k_gat_agg(const float* __restrict__ h,      // [N, HD]
                          const float* __restrict__ ssrc,   // [N, 4]
                          const float* __restrict__ sdst,   // [N, 4]
                          const int* __restrict__ off, const int* __restrict__ csr,
                          const float* __restrict__ bias,   // [256]
                          float* __restrict__ out, int N)   // [N, 256] (tf32-rounded)
{
    const int n = blockIdx.x;
    const int tid = threadIdx.x;      // 256
    const int e0 = off[n], e1 = off[n + 1];

    __shared__ int    s_src[AGG_CHUNK];
    __shared__ float  s_w[AGG_CHUNK * 4];
    __shared__ float4 red[256];
    __shared__ float  s_m[4], s_s[4];
    __shared__ float  s_out[1024];

    float sd[4];
#pragma unroll
    for (int hh = 0; hh < 4; hh++) sd[hh] = sdst[n * 4 + hh];

    float mloc[4] = {-1e30f, -1e30f, -1e30f, -1e30f};
    for (int e = e0 + tid; e < e1; e += 256) {
        int s = csr[e];
#pragma unroll
        for (int hh = 0; hh < 4; hh++) {
            float v = ssrc[s * 4 + hh] + sd[hh];
            v = v > 0.f ? v : 0.2f * v;
            mloc[hh] = fmaxf(mloc[hh], v);
        }
    }
    red[tid] = make_float4(mloc[0], mloc[1], mloc[2], mloc[3]);
    __syncthreads();
    for (int s = 128; s > 0; s >>= 1) {
        if (tid < s) {
            float4 a = red[tid], b = red[tid + s];
            a.x = fmaxf(a.x, b.x); a.y = fmaxf(a.y, b.y);
            a.z = fmaxf(a.z, b.z); a.w = fmaxf(a.w, b.w);
            red[tid] = a;
        }
        __syncthreads();
    }
    if (tid < 4) s_m[tid] = ((float*)&red[0])[tid];
    __syncthreads();
    float m0 = s_m[0], m1 = s_m[1], m2 = s_m[2], m3 = s_m[3];

    const int hh_ = tid >> 6;
    const int cb  = tid & 63;
    float acc0 = 0.f, acc1 = 0.f, acc2 = 0.f, acc3 = 0.f;
    float wsum[4] = {0.f, 0.f, 0.f, 0.f};

    for (int c0 = e0; c0 < e1; c0 += AGG_CHUNK) {
        int cnt = min(AGG_CHUNK, e1 - c0);
        for (int j = tid; j < cnt; j += 256) {
            int s = csr[c0 + j];
            s_src[j] = s;
            float v0 = ssrc[s * 4 + 0] + sd[0]; v0 = v0 > 0.f ? v0 : 0.2f * v0;
            float v1 = ssrc[s * 4 + 1] + sd[1]; v1 = v1 > 0.f ? v1 : 0.2f * v1;
            float v2 = ssrc[s * 4 + 2] + sd[2]; v2 = v2 > 0.f ? v2 : 0.2f * v2;
            float v3 = ssrc[s * 4 + 3] + sd[3]; v3 = v3 > 0.f ? v3 : 0.2f * v3;
            float w0 = __expf(v0 - m0), w1 = __expf(v1 - m1);
            float w2 = __expf(v2 - m2), w3 = __expf(v3 - m3);
            s_w[j * 4 + 0] = w0; s_w[j * 4 + 1] = w1;
            s_w[j * 4 + 2] = w2; s_w[j * 4 + 3] = w3;
            wsum[0] += w0; wsum[1] += w1; wsum[2] += w2; wsum[3] += w3;
        }
        __syncthreads();
        for (int j = 0; j < cnt; j++) {
            int s = s_src[j];
            float w = s_w[j * 4 + hh_];
            const float* hr = h + (size_t)s * HD + hh_ * DD + cb;
            acc0 += w * hr[0];
            acc1 += w * hr[64];
            acc2 += w * hr[128];
            acc3 += w * hr[192];
        }
        __syncthreads();
    }

    red[tid] = make_float4(wsum[0], wsum[1], wsum[2], wsum[3]);
    __syncthreads();
    for (int s = 128; s > 0; s >>= 1) {
        if (tid < s) {
            float4 a = red[tid], b = red[tid + s];
            a.x += b.x; a.y += b.y; a.z += b.z; a.w += b.w;
            red[tid] = a;
        }
        __syncthreads();
    }
    if (tid < 4) s_s[tid] = ((float*)&red[0])[tid];

    s_out[hh_ * 256 + cb]       = acc0;
    s_out[hh_ * 256 + cb + 64]  = acc1;
    s_out[hh_ * 256 + cb + 128] = acc2;
    s_out[hh_ * 256 + cb + 192] = acc3;
    __syncthreads();

    {
        int c = tid;
        float r = 0.f;
#pragma unroll
        for (int hh = 0; hh < 4; hh++)
            r += s_out[hh * 256 + c] / (s_s[hh] + 1e-16f);
        out[(size_t)n * DD + c] = f2tf_f(0.25f * r + bias[c]);
    }
}

// ---------------- fused concat + final FC ([768] -> 32) --------------------
__global__ void k_final(const float* __restrict__ d, const float* __restrict__ ai,
                        const float* __restrict__ ae, const float* __restrict__ W,
                        const float* __restrict__ b, float* __restrict__ out, int M)
{
    __shared__ float s_in[8][768];
    int r0 = blockIdx.x * 8;
    int tid = threadIdx.x;   // 256
    for (int idx = tid; idx < 8 * 768; idx += 256) {
        int rr = idx / 768, cc = idx - rr * 768;
        int r = r0 + rr;
        float v = 0.f;
        if (r < M) {
            if (cc < 256)      v = d [(size_t)r * 256 + cc];
            else if (cc < 512) v = ai[(size_t)r * 256 + cc - 256];
            else               v = ae[(size_t)r * 256 + cc - 512];
        }
        s_in[rr][cc] = v;
    }
    __syncthreads();
    int rr = tid >> 5, j = tid & 31;
    int r = r0 + rr;
    if (r < M) {
        float acc = b[j];
#pragma unroll 8
        for (int k = 0; k < 768; k++) acc += s_in[rr][k] * W[k * 32 + j];
        out[(size_t)r * 32 + j] = acc;
    }
}

// ---------------- host orchestration ---------------------------------------
enum { GM_PLAIN = 0, GM_BIASRELU = 1, GM_EXPSUM = 2, GM_NORM = 3 };

static bool g_attr_set = false;

static inline void launch_gemm(const float* A, const float* B, float* C,
                               const float* aux, float* rowsum,
                               int M, int N, int K, bool transb, int mode,
                               cudaStream_t st)
{
    if (!g_attr_set) {
        cudaFuncSetAttribute(tgemm<true,  GM_EXPSUM>,   cudaFuncAttributeMaxDynamicSharedMemorySize, TG_SMEM);
        cudaFuncSetAttribute(tgemm<false, GM_BIASRELU>, cudaFuncAttributeMaxDynamicSharedMemorySize, TG_SMEM);
        cudaFuncSetAttribute(tgemm<false, GM_NORM>,     cudaFuncAttributeMaxDynamicSharedMemorySize, TG_SMEM);
        cudaFuncSetAttribute(tgemm<false, GM_PLAIN>,    cudaFuncAttributeMaxDynamicSharedMemorySize, TG_SMEM);
        g_attr_set = true;
    }
    dim3 grid(N / 128, (M + 127) / 128);
    if (transb) {
        tgemm<true, GM_EXPSUM><<<grid, 256, TG_SMEM, st>>>(A, B, C, aux, rowsum, M, N, K);
    } else if (mode == GM_BIASRELU) {
        tgemm<false, GM_BIASRELU><<<grid, 256, TG_SMEM, st>>>(A, B, C, aux, rowsum, M, N, K);
    } else if (mode == GM_NORM) {
        tgemm<false, GM_NORM><<<grid, 256, TG_SMEM, st>>>(A, B, C, aux, rowsum, M, N, K);
    } else {
        tgemm<false, GM_PLAIN><<<grid, 256, TG_SMEM, st>>>(A, B, C, aux, rowsum, M, N, K);
    }
}

// x must already be tf32-rounded; W raw -> converted via per-branch wtmp.
static void run_gat(const float* x_tf, const float* W_raw, const float* a_src,
                    const float* a_dst, const float* bias,
                    const int* esrc, const int* edst,
                    int N, int E, int Din, float* hbuf, float* gat_out,
                    float* wtmp, float* ssrc, float* sdst,
                    int* deg, int* off, int* cur, int* csr,
                    cudaStream_t st)
{
    k_pretf<<<512, 256, 0, st>>>(W_raw, wtmp, Din * HD);
    launch_gemm(x_tf, wtmp, hbuf, nullptr, nullptr, N, HD, Din, false, GM_PLAIN, st);
    k_scores<<<N, 128, 0, st>>>(hbuf, a_src, a_dst, ssrc, sdst, N);
    k_set_deg1<<<(N + 255) / 256, 256, 0, st>>>(deg, N);
    int gE = (E + 255) / 256; if (gE > 2048) gE = 2048;
    k_count<<<gE, 256, 0, st>>>(edst, deg, E);
    k_exscan<<<1, 1024, 0, st>>>(deg, off, cur, N);
    k_fill<<<gE, 256, 0, st>>>(esrc, edst, cur, csr, E);
    k_fill_self<<<(N + 255) / 256, 256, 0, st>>>(cur, csr, N);
    k_gat_agg<<<N, 256, 0, st>>>(hbuf, ssrc, sdst, off, csr, bias, gat_out, N);
}

extern "C" void kernel_launch(void* const* d_in, const int* in_sizes, int n_in,
                              void* d_out, int out_size)
{
    const float* x_d     = (const float*)d_in[0];
    const int*   idx_i   = (const int*)  d_in[1];
    const int*   idx_e   = (const int*)  d_in[2];
    const int*   eidx_d  = (const int*)  d_in[3];
    const int*   eidx_i  = (const int*)  d_in[4];
    const int*   eidx_e  = (const int*)  d_in[5];
    const float* emb_i   = (const float*)d_in[6];
    const float* emb_e   = (const float*)d_in[7];
    const float* Wd      = (const float*)d_in[8];
    const float* a_src_d = (const float*)d_in[9];
    const float* a_dst_d = (const float*)d_in[10];
    const float* bd      = (const float*)d_in[11];
    const float* Wi      = (const float*)d_in[12];
    const float* a_src_i = (const float*)d_in[13];
    const float* a_dst_i = (const float*)d_in[14];
    const float* bi      = (const float*)d_in[15];
    const float* We      = (const float*)d_in[16];
    const float* a_src_e = (const float*)d_in[17];
    const float* a_dst_e = (const float*)d_in[18];
    const float* be      = (const float*)d_in[19];
    const float* W_dfc   = (const float*)d_in[20];
    const float* b_dfc   = (const float*)d_in[21];
    const float* W_ifc   = (const float*)d_in[22];
    const float* b_ifc   = (const float*)d_in[23];
    const float* W_efc   = (const float*)d_in[24];
    const float* b_efc   = (const float*)d_in[25];
    const float* W_fc    = (const float*)d_in[26];
    const float* b_fc    = (const float*)d_in[27];
    float* out = (float*)d_out;

    const int Din = 512;
    const int Nd = in_sizes[0] / Din;
    const int Ni = in_sizes[1];
    const int Ne = in_sizes[2];
    const int Ed = in_sizes[3] / 2;
    const int Ei = in_sizes[4] / 2;
    const int Ee = in_sizes[5] / 2;

    // --- pointers to device scratch ---
    float *hd, *hi, *he, *ie, *ee, *ssrc, *sdst, *ssrc2, *sdst2, *ssrc3, *sdst3;
    float *ssum, *ssum2, *gat, *gat2, *gat3, *dd, *ii, *ev, *S, *S2, *atti, *atte;
    float *wtmp, *wtmp2, *wtmp3;
    int *deg, *off, *cur, *csr, *deg2, *off2, *cur2, *csr2, *deg3, *off3, *cur3, *csr3;
    cudaGetSymbolAddress((void**)&hd,    g_hd);
    cudaGetSymbolAddress((void**)&hi,    g_hi);
    cudaGetSymbolAddress((void**)&he,    g_he);
    cudaGetSymbolAddress((void**)&ie,    g_ie);
    cudaGetSymbolAddress((void**)&ee,    g_ee);
    cudaGetSymbolAddress((void**)&ssrc,  g_ssrc);
    cudaGetSymbolAddress((void**)&sdst,  g_sdst);
    cudaGetSymbolAddress((void**)&ssrc2, g_ssrc2);
    cudaGetSymbolAddress((void**)&sdst2, g_sdst2);
    cudaGetSymbolAddress((void**)&ssrc3, g_ssrc3);
    cudaGetSymbolAddress((void**)&sdst3, g_sdst3);
    cudaGetSymbolAddress((void**)&ssum,  g_ssum);
    cudaGetSymbolAddress((void**)&ssum2, g_ssum2);
    cudaGetSymbolAddress((void**)&gat,   g_gat);
    cudaGetSymbolAddress((void**)&gat2,  g_gat2);
    cudaGetSymbolAddress((void**)&gat3,  g_gat3);
    cudaGetSymbolAddress((void**)&dd,    g_dd);
    cudaGetSymbolAddress((void**)&ii,    g_ii);
    cudaGetSymbolAddress((void**)&ev,    g_ev);
    cudaGetSymbolAddress((void**)&S,     g_S);
    cudaGetSymbolAddress((void**)&S2,    g_S2);
    cudaGetSymbolAddress((void**)&atti,  g_atti);
    cudaGetSymbolAddress((void**)&atte,  g_atte);
    cudaGetSymbolAddress((void**)&wtmp,  g_wtmp);
    cudaGetSymbolAddress((void**)&wtmp2, g_wtmp2);
    cudaGetSymbolAddress((void**)&wtmp3, g_wtmp3);
    cudaGetSymbolAddress((void**)&deg,   g_deg);
    cudaGetSymbolAddress((void**)&off,   g_off);
    cudaGetSymbolAddress((void**)&cur,   g_cur);
    cudaGetSymbolAddress((void**)&csr,   g_csr);
    cudaGetSymbolAddress((void**)&deg2,  g_deg2);
    cudaGetSymbolAddress((void**)&off2,  g_off2);
    cudaGetSymbolAddress((void**)&cur2,  g_cur2);
    cudaGetSymbolAddress((void**)&csr2,  g_csr2);
    cudaGetSymbolAddress((void**)&deg3,  g_deg3);
    cudaGetSymbolAddress((void**)&off3,  g_off3);
    cudaGetSymbolAddress((void**)&cur3,  g_cur3);
    cudaGetSymbolAddress((void**)&csr3,  g_csr3);

    // --- streams / events (created once; host-side resources only) ---
    static cudaStream_t s1 = nullptr, s2 = nullptr;
    static cudaEvent_t evRoot = nullptr, ev1 = nullptr, evD = nullptr, ev3 = nullptr;
    if (!s1) {
        cudaStreamCreateWithFlags(&s1, cudaStreamNonBlocking);
        cudaStreamCreateWithFlags(&s2, cudaStreamNonBlocking);
        cudaEventCreateWithFlags(&evRoot, cudaEventDisableTiming);
        cudaEventCreateWithFlags(&ev1,    cudaEventDisableTiming);
        cudaEventCreateWithFlags(&evD,    cudaEventDisableTiming);
        cudaEventCreateWithFlags(&ev3,    cudaEventDisableTiming);
    }
    cudaStream_t s0 = 0;   // capture-origin (legacy default) stream

    // ---- fork ----
    cudaEventRecord(evRoot, s0);
    cudaStreamWaitEvent(s1, evRoot, 0);
    cudaStreamWaitEvent(s2, evRoot, 0);

    // ---- intention branch on s1 ----
    k_gather_emb<<<1024, 256, 0, s1>>>(emb_i, idx_i, ie, Ni);
    run_gat(ie, Wi, a_src_i, a_dst_i, bi, eidx_i, eidx_i + Ei, Ni, Ei, DD,
            hi, gat2, wtmp2, ssrc2, sdst2, deg2, off2, cur2, csr2, s1);
    k_pretf<<<256, 256, 0, s1>>>(W_ifc, wtmp2, DD * DD);
    launch_gemm(gat2, wtmp2, ii, b_ifc, nullptr, Ni, DD, DD, false, GM_BIASRELU, s1);
    k_zero<<<(Nd + 255) / 256, 256, 0, s1>>>(ssum, Nd);
    cudaEventRecord(ev1, s1);

    // ---- emotion branch on s2 ----
    k_gather_emb<<<1024, 256, 0, s2>>>(emb_e, idx_e, ee, Ne);
    run_gat(ee, We, a_src_e, a_dst_e, be, eidx_e, eidx_e + Ee, Ne, Ee, DD,
            he, gat3, wtmp3, ssrc3, sdst3, deg3, off3, cur3, csr3, s2);
    k_pretf<<<256, 256, 0, s2>>>(W_efc, wtmp3, DD * DD);
    launch_gemm(gat3, wtmp3, ev, b_efc, nullptr, Ne, DD, DD, false, GM_BIASRELU, s2);
    k_zero<<<(Nd + 255) / 256, 256, 0, s2>>>(ssum2, Nd);

    // ---- dialogue branch on s0 ----
    float* x_tf = S;    // g_S free until chain-i EXPSUM (strictly later on s0)
    k_pretf<<<4096, 256, 0, s0>>>(x_d, x_tf, Nd * Din);
    run_gat(x_tf, Wd, a_src_d, a_dst_d, bd, eidx_d, eidx_d + Ed, Nd, Ed, Din,
            hd, gat, wtmp, ssrc, sdst, deg, off, cur, csr, s0);
    k_pretf<<<256, 256, 0, s0>>>(W_dfc, wtmp, DD * DD);
    launch_gemm(gat, wtmp, dd, b_dfc, nullptr, Nd, DD, DD, false, GM_BIASRELU, s0);
    cudaEventRecord(evD, s0);

    // ---- attention chain i on s0 (needs ii from s1) ----
    cudaStreamWaitEvent(s0, ev1, 0);
    launch_gemm(dd, ii, S, nullptr, ssum, Nd, Ni, DD, true, GM_EXPSUM, s0);
    launch_gemm(S, ii, atti, ssum, nullptr, Nd, DD, Ni, false, GM_NORM, s0);

    // ---- attention chain e on s2 (needs dd from s0) ----
    cudaStreamWaitEvent(s2, evD, 0);
    launch_gemm(dd, ev, S2, nullptr, ssum2, Nd, Ne, DD, true, GM_EXPSUM, s2);
    launch_gemm(S2, ev, atte, ssum2, nullptr, Nd, DD, Ne, false, GM_NORM, s2);
    cudaEventRecord(ev3, s2);

    // ---- join + final FC ----
    cudaStreamWaitEvent(s0, ev3, 0);
    k_final<<<(Nd + 7) / 8, 256, 0, s0>>>(dd, atti, atte, W_fc, b_fc, out, Nd);
}

// round 17
// speedup vs baseline: 2.2797x; 1.4636x over previous
#include <cuda_runtime.h>
#include <cuda_fp16.h>
#include <math.h>
#include <stdint.h>

#define HEADS 4
#define DD 256
#define HD 1024            // HEADS * DD

#define MAXND 20000
#define MAXNI 4096
#define MAXED 640000
#define MAXET (MAXED + MAXND)
#define MAXEI (MAXNI * 17)

// ---------------- scratch (device globals; no allocation allowed) ----------
__device__ __half g_hd  [(size_t)MAXND * HD];
__device__ __half g_hi  [(size_t)MAXNI * HD];
__device__ __half g_he  [(size_t)MAXNI * HD];
__device__ __half g_ie  [(size_t)MAXNI * DD];
__device__ __half g_ee  [(size_t)MAXNI * DD];
__device__ float g_ssrc [(size_t)MAXND * HEADS];
__device__ float g_sdst [(size_t)MAXND * HEADS];
__device__ float g_ssrc2[(size_t)MAXNI * HEADS];
__device__ float g_sdst2[(size_t)MAXNI * HEADS];
__device__ float g_ssrc3[(size_t)MAXNI * HEADS];
__device__ float g_sdst3[(size_t)MAXNI * HEADS];
__device__ float g_ssum [MAXND];
__device__ float g_ssum2[MAXND];
__device__ int   g_deg [MAXND];
__device__ int   g_off [MAXND + 1];
__device__ int   g_cur [MAXND];
__device__ int   g_csr [MAXET];
__device__ int   g_deg2[MAXNI];
__device__ int   g_off2[MAXNI + 1];
__device__ int   g_cur2[MAXNI];
__device__ int   g_csr2[MAXEI];
__device__ int   g_deg3[MAXNI];
__device__ int   g_off3[MAXNI + 1];
__device__ int   g_cur3[MAXNI];
__device__ int   g_csr3[MAXEI];
__device__ __half g_gat  [(size_t)MAXND * DD];
__device__ __half g_gat2 [(size_t)MAXNI * DD];   // later reused as iiT [256,4096]
__device__ __half g_gat3 [(size_t)MAXNI * DD];   // later reused as evT
__device__ __half g_dd  [(size_t)MAXND * DD];
__device__ __half g_ii  [(size_t)MAXNI * DD];
__device__ __half g_ev  [(size_t)MAXNI * DD];
__device__ __half g_S   [(size_t)MAXND * 4096];  // chain-i scores; also x_d half scratch
__device__ __half g_S2  [(size_t)MAXND * 4096];  // chain-e scores
__device__ __half g_atti[(size_t)MAXND * DD];
__device__ __half g_atte[(size_t)MAXND * DD];
__device__ __half g_wtmp [512 * 1024];           // transposed half weights
__device__ __half g_wtmp2[256 * 1024];
__device__ __half g_wtmp3[256 * 1024];

// ---------------- helpers ---------------------------------------------------
__device__ __forceinline__ uint32_t smem_u32(const void* p) {
    uint32_t a;
    asm("{ .reg .u64 t; cvta.to.shared.u64 t, %1; cvt.u32.u64 %0, t; }"
        : "=r"(a) : "l"(p));
    return a;
}
#define CPASYNC16(d, s) \
    asm volatile("cp.async.cg.shared.global [%0], [%1], 16;" \
                 :: "r"(d), "l"(s))
#define CPCOMMIT() asm volatile("cp.async.commit_group;")

// ---------------- fp16 tensor-core GEMM, cp.async 3-stage pipeline ----------
// C[M,N] (half) = A[M,K] @ Bt[N,K]^T, A/Bt half, fp32 accumulate.
// BM=BN=128, BK=32 (2 x k16), 256 threads = 8 warps (4x2), warp tile 32x64
// via mma.sync.m16n8k16. Requires N % 128 == 0, K % 32 == 0; M guarded.
// Smem rows padded to 40 halves (20 words) -> conflict-free fragment loads.
// MODE: 0 plain, 1 bias+relu, 2 exp + rowsum atomics, 3 divide by rowsum.
#define TG_SMEM 61440
template<int MODE>
__global__ __launch_bounds__(256)
void tgemmh(const __half* __restrict__ A, const __half* __restrict__ Bt,
            __half* __restrict__ C, const float* __restrict__ aux,
            float* __restrict__ rowsum, int M, int N, int K)
{
    extern __shared__ __half smh[];

    const int tid  = threadIdx.x;
    const int warp = tid >> 5, lane = tid & 31;
    const int g    = lane >> 2, tig = lane & 3;
    const int wm   = (warp >> 1) * 32;
    const int wn   = (warp & 1) * 64;
    const int row0 = blockIdx.y * 128, col0 = blockIdx.x * 128;

    float c[2][8][4];
#pragma unroll
    for (int i = 0; i < 2; i++)
#pragma unroll
        for (int j = 0; j < 8; j++)
#pragma unroll
            for (int q = 0; q < 4; q++) c[i][j][q] = 0.f;

    const uint32_t base_u32 = smem_u32(smh);
    const int nIter = K >> 5;

    // stage s (20480 B): A (128 x 40 halves = 10240 B) then Bt (10240 B)
    auto load_stage = [&](int s, int k0) {
        uint32_t ab = base_u32 + s * 20480;
        uint32_t bb = ab + 10240;
#pragma unroll
        for (int i = 0; i < 2; i++) {
            int q = tid + 256 * i;
            int r = q >> 2, cb = q & 3;          // row, 16B chunk (8 halves)
            int gr = row0 + r;
            const __half* srcA = A + (size_t)(gr < M ? gr : M - 1) * K + k0 + cb * 8;
            CPASYNC16(ab + r * 80 + cb * 16, srcA);
            const __half* srcB = Bt + (size_t)(col0 + r) * K + k0 + cb * 8;
            CPASYNC16(bb + r * 80 + cb * 16, srcB);
        }
        CPCOMMIT();
    };

    load_stage(0, 0);
    if (nIter > 1) load_stage(1, 32);

    int cur = 0, nxt2 = 2;
    for (int it = 0; it < nIter; it++) {
        if (it + 1 < nIter) {
            asm volatile("cp.async.wait_group 1;");
        } else {
            asm volatile("cp.async.wait_group 0;");
        }
        __syncthreads();

        if (it + 2 < nIter) load_stage(nxt2, (it + 2) << 5);

        const __half* as_ = smh + cur * 10240;
        const __half* bs_ = as_ + 5120;          // 10240 B = 5120 halves

#pragma unroll
        for (int ks = 0; ks < 2; ks++) {
            const int kk = ks * 16;
            uint32_t af[2][4], bf[8][2];
#pragma unroll
            for (int i = 0; i < 2; i++) {
                int m = wm + i * 16 + g;
                af[i][0] = *(const uint32_t*)(as_ + (size_t)m * 40 + kk + 2 * tig);
                af[i][1] = *(const uint32_t*)(as_ + (size_t)(m + 8) * 40 + kk + 2 * tig);
                af[i][2] = *(const uint32_t*)(as_ + (size_t)m * 40 + kk + 2 * tig + 8);
                af[i][3] = *(const uint32_t*)(as_ + (size_t)(m + 8) * 40 + kk + 2 * tig + 8);
            }
#pragma unroll
            for (int j = 0; j < 8; j++) {
                int n = wn + j * 8 + g;
                bf[j][0] = *(const uint32_t*)(bs_ + (size_t)n * 40 + kk + 2 * tig);
                bf[j][1] = *(const uint32_t*)(bs_ + (size_t)n * 40 + kk + 2 * tig + 8);
            }
#pragma unroll
            for (int i = 0; i < 2; i++)
#pragma unroll
                for (int j = 0; j < 8; j++) {
                    asm volatile(
                        "mma.sync.aligned.m16n8k16.row.col.f32.f16.f16.f32 "
                        "{%0,%1,%2,%3}, {%4,%5,%6,%7}, {%8,%9}, {%0,%1,%2,%3};"
                        : "+f"(c[i][j][0]), "+f"(c[i][j][1]),
                          "+f"(c[i][j][2]), "+f"(c[i][j][3])
                        : "r"(af[i][0]), "r"(af[i][1]), "r"(af[i][2]), "r"(af[i][3]),
                          "r"(bf[j][0]), "r"(bf[j][1]));
                }
        }

        cur = (cur + 1 == 3) ? 0 : cur + 1;
        nxt2 = (nxt2 + 1 == 3) ? 0 : nxt2 + 1;
    }

    // ---- epilogue ----
#pragma unroll
    for (int i = 0; i < 2; i++) {
        int r0 = row0 + wm + i * 16 + g;
        int r1 = r0 + 8;
        float inv0 = 1.f, inv1 = 1.f;
        if (MODE == 3) {
            if (r0 < M) inv0 = 1.f / (aux[r0] + 1e-16f);
            if (r1 < M) inv1 = 1.f / (aux[r1] + 1e-16f);
        }
        float p0 = 0.f, p1 = 0.f;
#pragma unroll
        for (int j = 0; j < 8; j++) {
            int cc = col0 + wn + j * 8 + tig * 2;
            float v0 = c[i][j][0], v1 = c[i][j][1];
            float v2 = c[i][j][2], v3 = c[i][j][3];
            if (MODE == 1) {
                float bb0 = aux[cc], bb1 = aux[cc + 1];
                v0 = fmaxf(v0 + bb0, 0.f); v1 = fmaxf(v1 + bb1, 0.f);
                v2 = fmaxf(v2 + bb0, 0.f); v3 = fmaxf(v3 + bb1, 0.f);
            }
            if (MODE == 2) {
                // round to half FIRST, accumulate the rounded value so that
                // rowsum is exactly the sum of the stored probabilities
                v0 = __half2float(__float2half_rn(__expf(v0)));
                v1 = __half2float(__float2half_rn(__expf(v1)));
                v2 = __half2float(__float2half_rn(__expf(v2)));
                v3 = __half2float(__float2half_rn(__expf(v3)));
                p0 += v0 + v1; p1 += v2 + v3;
            }
            if (MODE == 3) {
                v0 *= inv0; v1 *= inv0; v2 *= inv1; v3 *= inv1;
            }
            if (r0 < M) *(__half2*)(C + (size_t)r0 * N + cc) = __floats2half2_rn(v0, v1);
            if (r1 < M) *(__half2*)(C + (size_t)r1 * N + cc) = __floats2half2_rn(v2, v3);
        }
        if (MODE == 2) {
            p0 += __shfl_down_sync(0xffffffffu, p0, 1);
            p0 += __shfl_down_sync(0xffffffffu, p0, 2);
            p1 += __shfl_down_sync(0xffffffffu, p1, 1);
            p1 += __shfl_down_sync(0xffffffffu, p1, 2);
            if (tig == 0) {
                if (r0 < M) atomicAdd(&rowsum[r0], p0);
                if (r1 < M) atomicAdd(&rowsum[r1], p1);
            }
        }
    }
}

// ---------------- misc small kernels ---------------------------------------
__global__ void k_zero(float* __restrict__ p, int n)
{
    int i = blockIdx.x * blockDim.x + threadIdx.x;
    if (i < n) p[i] = 0.f;
}

// float -> half elementwise
__global__ void k_preh(const float* __restrict__ in, __half* __restrict__ out, int n)
{
    int i = blockIdx.x * blockDim.x + threadIdx.x;
    for (; i < n; i += gridDim.x * blockDim.x) out[i] = __float2half_rn(in[i]);
}

// float [R, C] -> half [C, R] (transpose + convert)
__global__ void k_preh_T(const float* __restrict__ in, __half* __restrict__ out,
                         int R, int C)
{
    __shared__ float t[32][33];
    int cb = blockIdx.x * 32, rb = blockIdx.y * 32;
    int x = threadIdx.x, y0 = threadIdx.y;   // 32 x 8
    for (int dy = y0; dy < 32; dy += 8) {
        int rr = rb + dy, cc = cb + x;
        t[dy][x] = (rr < R && cc < C) ? in[(size_t)rr * C + cc] : 0.f;
    }
    __syncthreads();
    for (int dy = y0; dy < 32; dy += 8) {
        int cc = cb + dy, rr = rb + x;
        if (cc < C && rr < R) out[(size_t)cc * R + rr] = __float2half_rn(t[x][dy]);
    }
}

// half [R, C] -> half [C, R]
__global__ void k_tr_h(const __half* __restrict__ in, __half* __restrict__ out,
                       int R, int C)
{
    __shared__ __half t[32][34];
    int cb = blockIdx.x * 32, rb = blockIdx.y * 32;
    int x = threadIdx.x, y0 = threadIdx.y;   // 32 x 8
    for (int dy = y0; dy < 32; dy += 8) {
        int rr = rb + dy, cc = cb + x;
        t[dy][x] = (rr < R && cc < C) ? in[(size_t)rr * C + cc] : __half(0.f);
    }
    __syncthreads();
    for (int dy = y0; dy < 32; dy += 8) {
        int cc = cb + dy, rr = rb + x;
        if (cc < C && rr < R) out[(size_t)cc * R + rr] = t[x][dy];
    }
}

__global__ void k_gather_emb(const float* __restrict__ table, const int* __restrict__ idx,
                             __half* __restrict__ out, int N)
{
    int i = blockIdx.x * blockDim.x + threadIdx.x;
    int total = N * DD;
    for (; i < total; i += gridDim.x * blockDim.x) {
        int n = i / DD, c = i - n * DD;
        out[i] = __float2half_rn(table[(size_t)idx[n] * DD + c]);
    }
}

__global__ void k_scores(const __half* __restrict__ h, const float* __restrict__ a_src,
                         const float* __restrict__ a_dst,
                         float* __restrict__ ssrc, float* __restrict__ sdst, int N)
{
    int n = blockIdx.x;
    int tid = threadIdx.x;        // 128
    int hh = tid >> 5, lane = tid & 31;
    const __half* hr = h + (size_t)n * HD + hh * DD;
    float s1 = 0.f, s2 = 0.f;
    for (int c = lane; c < DD; c += 32) {
        float v = __half2float(hr[c]);
        s1 += v * a_src[hh * DD + c];
        s2 += v * a_dst[hh * DD + c];
    }
#pragma unroll
    for (int o = 16; o > 0; o >>= 1) {
        s1 += __shfl_down_sync(0xffffffffu, s1, o);
        s2 += __shfl_down_sync(0xffffffffu, s2, o);
    }
    if (lane == 0) { ssrc[n * HEADS + hh] = s1; sdst[n * HEADS + hh] = s2; }
}

__global__ void k_set_deg1(int* deg, int N)
{
    int i = blockIdx.x * blockDim.x + threadIdx.x;
    if (i < N) deg[i] = 1;
}
__global__ void k_count(const int* __restrict__ dst, int* __restrict__ deg, int E)
{
    int i = blockIdx.x * blockDim.x + threadIdx.x;
    for (; i < E; i += gridDim.x * blockDim.x) atomicAdd(&deg[dst[i]], 1);
}

__global__ void k_exscan(const int* __restrict__ deg, int* __restrict__ off,
                         int* __restrict__ cur, int N)
{
    __shared__ int wsum[32];
    __shared__ int carry_s;
    int tid = threadIdx.x, lane = tid & 31, w = tid >> 5;
    if (tid == 0) carry_s = 0;
    __syncthreads();
    for (int base = 0; base < N; base += 1024) {
        int i = base + tid;
        int v = (i < N) ? deg[i] : 0;
        int x = v;
#pragma unroll
        for (int o = 1; o < 32; o <<= 1) {
            int t = __shfl_up_sync(0xffffffffu, x, o);
            if (lane >= o) x += t;
        }
        if (lane == 31) wsum[w] = x;
        __syncthreads();
        if (w == 0) {
            int s = wsum[lane];
#pragma unroll
            for (int o = 1; o < 32; o <<= 1) {
                int t = __shfl_up_sync(0xffffffffu, s, o);
                if (lane >= o) s += t;
            }
            wsum[lane] = s;
        }
        __syncthreads();
        int excl = carry_s + (w > 0 ? wsum[w - 1] : 0) + x - v;
        if (i < N) { off[i] = excl; cur[i] = excl; }
        __syncthreads();
        if (tid == 0) carry_s += wsum[31];
        __syncthreads();
    }
    if (tid == 0) off[N] = carry_s;
}
__global__ void k_fill(const int* __restrict__ src, const int* __restrict__ dst,
                       int* __restrict__ cur, int* __restrict__ csr, int E)
{
    int i = blockIdx.x * blockDim.x + threadIdx.x;
    for (; i < E; i += gridDim.x * blockDim.x) {
        int p = atomicAdd(&cur[dst[i]], 1);
        csr[p] = src[i];
    }
}
__global__ void k_fill_self(int* __restrict__ cur, int* __restrict__ csr, int N)
{
    int i = blockIdx.x * blockDim.x + threadIdx.x;
    if (i < N) { int p = atomicAdd(&cur[i], 1); csr[p] = i; }
}

// ---------------- GAT aggregation: one block per destination node ----------
#define AGG_CHUNK 512
__global__ void k_gat_agg(const __half* __restrict__ h,     // [N, HD] half
                          const float* __restrict__ ssrc,
                          const float* __restrict__ sdst,
                          const int* __restrict__ off, const int* __restrict__ csr,
                          const float* __restrict__ bias,
                          __half* __restrict__ out, int N)  // [N, 256] half
{
    const int n = blockIdx.x;
    const int tid = threadIdx.x;      // 256
    const int e0 = off[n], e1 = off[n + 1];

    __shared__ int    s_src[AGG_CHUNK];
    __shared__ float  s_w[AGG_CHUNK * 4];
    __shared__ float4 red[256];
    __shared__ float  s_m[4], s_s[4];
    __shared__ float  s_out[1024];

    float sd[4];
#pragma unroll
    for (int hh = 0; hh < 4; hh++) sd[hh] = sdst[n * 4 + hh];

    float mloc[4] = {-1e30f, -1e30f, -1e30f, -1e30f};
    for (int e = e0 + tid; e < e1; e += 256) {
        int s = csr[e];
#pragma unroll
        for (int hh = 0; hh < 4; hh++) {
            float v = ssrc[s * 4 + hh] + sd[hh];
            v = v > 0.f ? v : 0.2f * v;
            mloc[hh] = fmaxf(mloc[hh], v);
        }
    }
    red[tid] = make_float4(mloc[0], mloc[1], mloc[2], mloc[3]);
    __syncthreads();
    for (int s = 128; s > 0; s >>= 1) {
        if (tid < s) {
            float4 a = red[tid], b = red[tid + s];
            a.x = fmaxf(a.x, b.x); a.y = fmaxf(a.y, b.y);
            a.z = fmaxf(a.z, b.z); a.w = fmaxf(a.w, b.w);
            red[tid] = a;
        }
        __syncthreads();
    }
    if (tid < 4) s_m[tid] = ((float*)&red[0])[tid];
    __syncthreads();
    float m0 = s_m[0], m1 = s_m[1], m2 = s_m[2], m3 = s_m[3];

    const int hh_ = tid >> 6;
    const int cb  = tid & 63;
    float acc0 = 0.f, acc1 = 0.f, acc2 = 0.f, acc3 = 0.f;
    float wsum[4] = {0.f, 0.f, 0.f, 0.f};

    for (int c0 = e0; c0 < e1; c0 += AGG_CHUNK) {
        int cnt = min(AGG_CHUNK, e1 - c0);
        for (int j = tid; j < cnt; j += 256) {
            int s = csr[c0 + j];
            s_src[j] = s;
            float v0 = ssrc[s * 4 + 0] + sd[0]; v0 = v0 > 0.f ? v0 : 0.2f * v0;
            float v1 = ssrc[s * 4 + 1] + sd[1]; v1 = v1 > 0.f ? v1 : 0.2f * v1;
            float v2 = ssrc[s * 4 + 2] + sd[2]; v2 = v2 > 0.f ? v2 : 0.2f * v2;
            float v3 = ssrc[s * 4 + 3] + sd[3]; v3 = v3 > 0.f ? v3 : 0.2f * v3;
            float w0 = __expf(v0 - m0), w1 = __expf(v1 - m1);
            float w2 = __expf(v2 - m2), w3 = __expf(v3 - m3);
            s_w[j * 4 + 0] = w0; s_w[j * 4 + 1] = w1;
            s_w[j * 4 + 2] = w2; s_w[j * 4 + 3] = w3;
            wsum[0] += w0; wsum[1] += w1; wsum[2] += w2; wsum[3] += w3;
        }
        __syncthreads();
        for (int j = 0; j < cnt; j++) {
            int s = s_src[j];
            float w = s_w[j * 4 + hh_];
            const __half* hr = h + (size_t)s * HD + hh_ * DD + cb;
            acc0 += w * __half2float(hr[0]);
            acc1 += w * __half2float(hr[64]);
            acc2 += w * __half2float(hr[128]);
            acc3 += w * __half2float(hr[192]);
        }
        __syncthreads();
    }

    red[tid] = make_float4(wsum[0], wsum[1], wsum[2], wsum[3]);
    __syncthreads();
    for (int s = 128; s > 0; s >>= 1) {
        if (tid < s) {
            float4 a = red[tid], b = red[tid + s];
            a.x += b.x; a.y += b.y; a.z += b.z; a.w += b.w;
            red[tid] = a;
        }
        __syncthreads();
    }
    if (tid < 4) s_s[tid] = ((float*)&red[0])[tid];

    s_out[hh_ * 256 + cb]       = acc0;
    s_out[hh_ * 256 + cb + 64]  = acc1;
    s_out[hh_ * 256 + cb + 128] = acc2;
    s_out[hh_ * 256 + cb + 192] = acc3;
    __syncthreads();

    {
        int c = tid;
        float r = 0.f;
#pragma unroll
        for (int hh = 0; hh < 4; hh++)
            r += s_out[hh * 256 + c] / (s_s[hh] + 1e-16f);
        out[(size_t)n * DD + c] = __float2half_rn(0.25f * r + bias[c]);
    }
}

// ---------------- fused concat + final FC ([768] -> 32) --------------------
__global__ void k_final(const __half* __restrict__ d, const __half* __restrict__ ai,
                        const __half* __restrict__ ae, const float* __restrict__ W,
                        const float* __restrict__ b, float* __restrict__ out, int M)
{
    __shared__ float s_in[8][768];
    int r0 = blockIdx.x * 8;
    int tid = threadIdx.x;   // 256
    for (int idx = tid; idx < 8 * 768; idx += 256) {
        int rr = idx / 768, cc = idx - rr * 768;
        int r = r0 + rr;
        float v = 0.f;
        if (r < M) {
            if (cc < 256)      v = __half2float(d [(size_t)r * 256 + cc]);
            else if (cc < 512) v = __half2float(ai[(size_t)r * 256 + cc - 256]);
            else               v = __half2float(ae[(size_t)r * 256 + cc - 512]);
        }
        s_in[rr][cc] = v;
    }
    __syncthreads();
    int rr = tid >> 5, j = tid & 31;
    int r = r0 + rr;
    if (r < M) {
        float acc = b[j];
#pragma unroll 8
        for (int k = 0; k < 768; k++) acc += s_in[rr][k] * W[k * 32 + j];
        out[(size_t)r * 32 + j] = acc;
    }
}

// ---------------- host orchestration ---------------------------------------
enum { GM_PLAIN = 0, GM_BIASRELU = 1, GM_EXPSUM = 2, GM_NORM = 3 };

static bool g_attr_set = false;

static inline void launch_gh(const __half* A, const __half* Bt, __half* C,
                             const float* aux, float* rowsum,
                             int M, int N, int K, int mode, cudaStream_t st)
{
    if (!g_attr_set) {
        cudaFuncSetAttribute(tgemmh<GM_PLAIN>,    cudaFuncAttributeMaxDynamicSharedMemorySize, TG_SMEM);
        cudaFuncSetAttribute(tgemmh<GM_BIASRELU>, cudaFuncAttributeMaxDynamicSharedMemorySize, TG_SMEM);
        cudaFuncSetAttribute(tgemmh<GM_EXPSUM>,   cudaFuncAttributeMaxDynamicSharedMemorySize, TG_SMEM);
        cudaFuncSetAttribute(tgemmh<GM_NORM>,     cudaFuncAttributeMaxDynamicSharedMemorySize, TG_SMEM);
        g_attr_set = true;
    }
    dim3 grid(N / 128, (M + 127) / 128);
    if (mode == GM_PLAIN)
        tgemmh<GM_PLAIN><<<grid, 256, TG_SMEM, st>>>(A, Bt, C, aux, rowsum, M, N, K);
    else if (mode == GM_BIASRELU)
        tgemmh<GM_BIASRELU><<<grid, 256, TG_SMEM, st>>>(A, Bt, C, aux, rowsum, M, N, K);
    else if (mode == GM_EXPSUM)
        tgemmh<GM_EXPSUM><<<grid, 256, TG_SMEM, st>>>(A, Bt, C, aux, rowsum, M, N, K);
    else
        tgemmh<GM_NORM><<<grid, 256, TG_SMEM, st>>>(A, Bt, C, aux, rowsum, M, N, K);
}

// x half; W raw float [Din, HD] -> transposed half wtmp [HD, Din].
static void run_gat(const __half* x_h, const float* W_raw, const float* a_src,
                    const float* a_dst, const float* bias,
                    const int* esrc, const int* edst,
                    int N, int E, int Din, __half* hbuf, __half* gat_out,
                    __half* wtmp, float* ssrc, float* sdst,
                    int* deg, int* off, int* cur, int* csr,
                    cudaStream_t st)
{
    dim3 tb(32, 8);
    k_preh_T<<<dim3(HD / 32, (Din + 31) / 32), tb, 0, st>>>(W_raw, wtmp, Din, HD);
    launch_gh(x_h, wtmp, hbuf, nullptr, nullptr, N, HD, Din, GM_PLAIN, st);
    k_scores<<<N, 128, 0, st>>>(hbuf, a_src, a_dst, ssrc, sdst, N);
    k_set_deg1<<<(N + 255) / 256, 256, 0, st>>>(deg, N);
    int gE = (E + 255) / 256; if (gE > 2048) gE = 2048;
    k_count<<<gE, 256, 0, st>>>(edst, deg, E);
    k_exscan<<<1, 1024, 0, st>>>(deg, off, cur, N);
    k_fill<<<gE, 256, 0, st>>>(esrc, edst, cur, csr, E);
    k_fill_self<<<(N + 255) / 256, 256, 0, st>>>(cur, csr, N);
    k_gat_agg<<<N, 256, 0, st>>>(hbuf, ssrc, sdst, off, csr, bias, gat_out, N);
}

extern "C" void kernel_launch(void* const* d_in, const int* in_sizes, int n_in,
                              void* d_out, int out_size)
{
    const float* x_d     = (const float*)d_in[0];
    const int*   idx_i   = (const int*)  d_in[1];
    const int*   idx_e   = (const int*)  d_in[2];
    const int*   eidx_d  = (const int*)  d_in[3];
    const int*   eidx_i  = (const int*)  d_in[4];
    const int*   eidx_e  = (const int*)  d_in[5];
    const float* emb_i   = (const float*)d_in[6];
    const float* emb_e   = (const float*)d_in[7];
    const float* Wd      = (const float*)d_in[8];
    const float* a_src_d = (const float*)d_in[9];
    const float* a_dst_d = (const float*)d_in[10];
    const float* bd      = (const float*)d_in[11];
    const float* Wi      = (const float*)d_in[12];
    const float* a_src_i = (const float*)d_in[13];
    const float* a_dst_i = (const float*)d_in[14];
    const float* bi      = (const float*)d_in[15];
    const float* We      = (const float*)d_in[16];
    const float* a_src_e = (const float*)d_in[17];
    const float* a_dst_e = (const float*)d_in[18];
    const float* be      = (const float*)d_in[19];
    const float* W_dfc   = (const float*)d_in[20];
    const float* b_dfc   = (const float*)d_in[21];
    const float* W_ifc   = (const float*)d_in[22];
    const float* b_ifc   = (const float*)d_in[23];
    const float* W_efc   = (const float*)d_in[24];
    const float* b_efc   = (const float*)d_in[25];
    const float* W_fc    = (const float*)d_in[26];
    const float* b_fc    = (const float*)d_in[27];
    float* out = (float*)d_out;

    const int Din = 512;
    const int Nd = in_sizes[0] / Din;
    const int Ni = in_sizes[1];
    const int Ne = in_sizes[2];
    const int Ed = in_sizes[3] / 2;
    const int Ei = in_sizes[4] / 2;
    const int Ee = in_sizes[5] / 2;

    __half *hd, *hi, *he, *ie, *ee, *gat, *gat2, *gat3, *dd, *ii, *ev, *S, *S2, *atti, *atte;
    __half *wtmp, *wtmp2, *wtmp3;
    float *ssrc, *sdst, *ssrc2, *sdst2, *ssrc3, *sdst3, *ssum, *ssum2;
    int *deg, *off, *cur, *csr, *deg2, *off2, *cur2, *csr2, *deg3, *off3, *cur3, *csr3;
    cudaGetSymbolAddress((void**)&hd,    g_hd);
    cudaGetSymbolAddress((void**)&hi,    g_hi);
    cudaGetSymbolAddress((void**)&he,    g_he);
    cudaGetSymbolAddress((void**)&ie,    g_ie);
    cudaGetSymbolAddress((void**)&ee,    g_ee);
    cudaGetSymbolAddress((void**)&ssrc,  g_ssrc);
    cudaGetSymbolAddress((void**)&sdst,  g_sdst);
    cudaGetSymbolAddress((void**)&ssrc2, g_ssrc2);
    cudaGetSymbolAddress((void**)&sdst2, g_sdst2);
    cudaGetSymbolAddress((void**)&ssrc3, g_ssrc3);
    cudaGetSymbolAddress((void**)&sdst3, g_sdst3);
    cudaGetSymbolAddress((void**)&ssum,  g_ssum);
    cudaGetSymbolAddress((void**)&ssum2, g_ssum2);
    cudaGetSymbolAddress((void**)&gat,   g_gat);
    cudaGetSymbolAddress((void**)&gat2,  g_gat2);
    cudaGetSymbolAddress((void**)&gat3,  g_gat3);
    cudaGetSymbolAddress((void**)&dd,    g_dd);
    cudaGetSymbolAddress((void**)&ii,    g_ii);
    cudaGetSymbolAddress((void**)&ev,    g_ev);
    cudaGetSymbolAddress((void**)&S,     g_S);
    cudaGetSymbolAddress((void**)&S2,    g_S2);
    cudaGetSymbolAddress((void**)&atti,  g_atti);
    cudaGetSymbolAddress((void**)&atte,  g_atte);
    cudaGetSymbolAddress((void**)&wtmp,  g_wtmp);
    cudaGetSymbolAddress((void**)&wtmp2, g_wtmp2);
    cudaGetSymbolAddress((void**)&wtmp3, g_wtmp3);
    cudaGetSymbolAddress((void**)&deg,   g_deg);
    cudaGetSymbolAddress((void**)&off,   g_off);
    cudaGetSymbolAddress((void**)&cur,   g_cur);
    cudaGetSymbolAddress((void**)&csr,   g_csr);
    cudaGetSymbolAddress((void**)&deg2,  g_deg2);
    cudaGetSymbolAddress((void**)&off2,  g_off2);
    cudaGetSymbolAddress((void**)&cur2,  g_cur2);
    cudaGetSymbolAddress((void**)&csr2,  g_csr2);
    cudaGetSymbolAddress((void**)&deg3,  g_deg3);
    cudaGetSymbolAddress((void**)&off3,  g_off3);
    cudaGetSymbolAddress((void**)&cur3,  g_cur3);
    cudaGetSymbolAddress((void**)&csr3,  g_csr3);

    static cudaStream_t s1 = nullptr, s2 = nullptr;
    static cudaEvent_t evRoot = nullptr, ev1 = nullptr, evD = nullptr, ev3 = nullptr;
    if (!s1) {
        cudaStreamCreateWithFlags(&s1, cudaStreamNonBlocking);
        cudaStreamCreateWithFlags(&s2, cudaStreamNonBlocking);
        cudaEventCreateWithFlags(&evRoot, cudaEventDisableTiming);
        cudaEventCreateWithFlags(&ev1,    cudaEventDisableTiming);
        cudaEventCreateWithFlags(&evD,    cudaEventDisableTiming);
        cudaEventCreateWithFlags(&ev3,    cudaEventDisableTiming);
    }
    cudaStream_t s0 = 0;
    dim3 tb(32, 8);

    // ---- fork ----
    cudaEventRecord(evRoot, s0);
    cudaStreamWaitEvent(s1, evRoot, 0);
    cudaStreamWaitEvent(s2, evRoot, 0);

    // ---- intention branch on s1 ----
    k_gather_emb<<<1024, 256, 0, s1>>>(emb_i, idx_i, ie, Ni);
    run_gat(ie, Wi, a_src_i, a_dst_i, bi, eidx_i, eidx_i + Ei, Ni, Ei, DD,
            hi, gat2, wtmp2, ssrc2, sdst2, deg2, off2, cur2, csr2, s1);
    k_preh_T<<<dim3(8, 8), tb, 0, s1>>>(W_ifc, wtmp2, DD, DD);
    launch_gh(gat2, wtmp2, ii, b_ifc, nullptr, Ni, DD, DD, GM_BIASRELU, s1);
    k_tr_h<<<dim3(8, 128), tb, 0, s1>>>(ii, gat2, Ni, DD);   // iiT [256, 4096]
    k_zero<<<(Nd + 255) / 256, 256, 0, s1>>>(ssum, Nd);
    cudaEventRecord(ev1, s1);

    // ---- emotion branch on s2 ----
    k_gather_emb<<<1024, 256, 0, s2>>>(emb_e, idx_e, ee, Ne);
    run_gat(ee, We, a_src_e, a_dst_e, be, eidx_e, eidx_e + Ee, Ne, Ee, DD,
            he, gat3, wtmp3, ssrc3, sdst3, deg3, off3, cur3, csr3, s2);
    k_preh_T<<<dim3(8, 8), tb, 0, s2>>>(W_efc, wtmp3, DD, DD);
    launch_gh(gat3, wtmp3, ev, b_efc, nullptr, Ne, DD, DD, GM_BIASRELU, s2);
    k_tr_h<<<dim3(8, 128), tb, 0, s2>>>(ev, gat3, Ne, DD);   // evT [256, 4096]
    k_zero<<<(Nd + 255) / 256, 256, 0, s2>>>(ssum2, Nd);

    // ---- dialogue branch on s0 ----
    __half* x_h = S;    // g_S free until chain-i EXPSUM (strictly later on s0)
    k_preh<<<4096, 256, 0, s0>>>(x_d, x_h, Nd * Din);
    run_gat(x_h, Wd, a_src_d, a_dst_d, bd, eidx_d, eidx_d + Ed, Nd, Ed, Din,
            hd, gat, wtmp, ssrc, sdst, deg, off, cur, csr, s0);
    k_preh_T<<<dim3(8, 8), tb, 0, s0>>>(W_dfc, wtmp, DD, DD);
    launch_gh(gat, wtmp, dd, b_dfc, nullptr, Nd, DD, DD, GM_BIASRELU, s0);
    cudaEventRecord(evD, s0);

    // ---- attention chain i on s0 (needs ii/iiT from s1) ----
    cudaStreamWaitEvent(s0, ev1, 0);
    launch_gh(dd, ii, S, nullptr, ssum, Nd, Ni, DD, GM_EXPSUM, s0);
    launch_gh(S, gat2, atti, ssum, nullptr, Nd, DD, Ni, GM_NORM, s0);

    // ---- attention chain e on s2 (needs dd from s0) ----
    cudaStreamWaitEvent(s2, evD, 0);
    launch_gh(dd, ev, S2, nullptr, ssum2, Nd, Ne, DD, GM_EXPSUM, s2);
    launch_gh(S2, gat3, atte, ssum2, nullptr, Nd, DD, Ne, GM_NORM, s2);
    cudaEventRecord(ev3, s2);

    // ---- join + final FC ----
    cudaStreamWaitEvent(s0, ev3, 0);
    k_final<<<(Nd + 7) / 8, 256, 0, s0>>>(dd, atti, atte, W_fc, b_fc, out, Nd);
}